// round 12
// baseline (speedup 1.0000x reference)
#include <cuda_runtime.h>
#include <cstdint>
#include <cstddef>

// Channel self-attention via Gram restructuring:
//   G_b = X X^T, s_b = X 1
//   E = Wq G Wk^T + (Wq s) bk^T + bq (Wk s)^T + N bq bk^T ; A = softmax(E)
//   M = gamma * Wo (A Wv) ; c = gamma * (Wo A bv + bo)
//   out = M X + c 1^T + X
//
// Inner GEMM loops feed raw fp32 bits to tf32 mma (HW truncates mantissa).
// Small warp tiles (32x32, acc=32 regs) -> 3 CTAs/SM -> 6 warps/SMSP for
// latency hiding. E-path keeps tf32x2 rna splits.

#define NTOK 36864
#define NCH 128
#define NBAT 8
#define NCHUNK 36
#define CHUNK 1024
#define GW 64     /* gram stage width (cols) */
#define GSTR 68   /* gram smem stride; 68%32==4 -> conflict-free */
#define LDSM 132
#define TOKT 64
#define XST 72    /* X stage stride; 72%32==8 -> conflict-free B frags */

__device__ float g_Gpart[NCHUNK * NBAT * NCH * NCH];
__device__ float g_spart[NCHUNK * NBAT * NCH];
__device__ float g_G[NBAT * NCH * NCH];
__device__ float g_s[NBAT * NCH];
__device__ uint32_t g_Mf[NBAT * 16384];   // M in tf32, mma-fragment-packed
__device__ float g_cvec[NBAT * NCH];

__device__ __forceinline__ uint32_t f2tf32(float f) {
    uint32_t u;
    asm("cvt.rna.tf32.f32 %0, %1;" : "=r"(u) : "f"(f));
    return u;
}

__device__ __forceinline__ void tf32split(float f, uint32_t& hi, uint32_t& lo) {
    uint32_t h;
    asm("cvt.rna.tf32.f32 %0, %1;" : "=r"(h) : "f"(f));
    float fh = __uint_as_float(h);
    float r = f - fh;
    uint32_t l;
    asm("cvt.rna.tf32.f32 %0, %1;" : "=r"(l) : "f"(r));
    hi = h; lo = l;
}

__device__ __forceinline__ void mma8(float* d, const uint32_t* a, uint32_t b0, uint32_t b1) {
    asm volatile(
        "mma.sync.aligned.m16n8k8.row.col.f32.tf32.tf32.f32 "
        "{%0,%1,%2,%3},{%4,%5,%6,%7},{%8,%9},{%0,%1,%2,%3};"
        : "+f"(d[0]), "+f"(d[1]), "+f"(d[2]), "+f"(d[3])
        : "r"(a[0]), "r"(a[1]), "r"(a[2]), "r"(a[3]), "r"(b0), "r"(b1));
}

__device__ __forceinline__ void cpa16(uint32_t dst, const void* src) {
    asm volatile("cp.async.cg.shared.global [%0],[%1],16;" :: "r"(dst), "l"(src));
}

// Fragment-packed M index: element (r, c) of the 128x128 matrix ->
// [kt(16)][mtile(8)][lane(32)][q(4)], lane = 4*grp+tq, q = qhi*2+qlo.
__device__ __forceinline__ int mf_index(int r, int c) {
    int kt = c >> 3, w = c & 7, qhi = w >> 2, tq = w & 3;
    int mtile = r >> 4, rr = r & 15, qlo = rr >> 3, grp = rr & 7;
    return ((kt * 8 + mtile) * 32 + grp * 4 + tq) * 4 + qhi * 2 + qlo;
}

// ---------------------------------------------------------------------------
// Gram: grid (chunk, nhalf, batch). Each CTA computes a 128x64 slice of the
// partial Gram over its 1024-col chunk (stage = all 128 rows x 64 cols,
// double-buffered). Twin CTAs (h=0/1) stream identical X -> L2 dedups.
// 32x32 warp tiles, acc=32 regs, 3 CTAs/SM. Deterministic.
// ---------------------------------------------------------------------------
__global__ __launch_bounds__(256, 3) void k_gram(const float* __restrict__ x) {
    extern __shared__ float sb[];   // 2 x 128 x GSTR = 69632 B
    int ch = blockIdx.x, h = blockIdx.y, b = blockIdx.z;
    int t = threadIdx.x;
    int lrow = t >> 1, lcol = (t & 1) << 5;
    int lane = t & 31, wid = t >> 5;
    int grp = lane >> 2, tq = lane & 3;
    int wm = wid & 3, wn = wid >> 2;   // wn in {0,1}: 32-col half of this CTA's 64

    const float* gsrc = x + (size_t)b * NCH * NTOK + (size_t)lrow * NTOK
                          + (size_t)ch * CHUNK + lcol;
    uint32_t sd0 = (uint32_t)__cvta_generic_to_shared(sb + lrow * GSTR + lcol);
    uint32_t sd1 = (uint32_t)__cvta_generic_to_shared(sb + NCH * GSTR + lrow * GSTR + lcol);

    float acc[2][4][4];
    #pragma unroll
    for (int i = 0; i < 2; i++)
        #pragma unroll
        for (int j = 0; j < 4; j++)
            #pragma unroll
            for (int k = 0; k < 4; k++) acc[i][j][k] = 0.f;
    float rsum = 0.f;

    #pragma unroll
    for (int j = 0; j < 8; j++) cpa16(sd0 + j * 16, gsrc + j * 4);
    asm volatile("cp.async.commit_group;");

    const int NST = CHUNK / GW;  // 16
    for (int s = 0; s < NST; s++) {
        if (s + 1 < NST) {
            uint32_t dd = ((s + 1) & 1) ? sd1 : sd0;
            const float* p = gsrc + (s + 1) * GW;
            #pragma unroll
            for (int j = 0; j < 8; j++) cpa16(dd + j * 16, p + j * 4);
            asm volatile("cp.async.commit_group;");
            asm volatile("cp.async.wait_group 1;");
        } else {
            asm volatile("cp.async.wait_group 0;");
        }
        __syncthreads();
        const float* cur = sb + (s & 1) * NCH * GSTR;
        const uint32_t* curu = (const uint32_t*)cur;

        if (h == 0) {   // only h=0 twins accumulate row sums
            const float4* rp4 = (const float4*)(cur + lrow * GSTR + lcol);
            #pragma unroll
            for (int i = 0; i < 8; i++) {
                float4 v = rp4[i];
                rsum += v.x + v.y + v.z + v.w;
            }
        }

        #pragma unroll
        for (int ks = 0; ks < 8; ks++) {
            int kk = ks * 8;
            uint32_t a[2][4];
            #pragma unroll
            for (int mt = 0; mt < 2; mt++) {
                int r0 = wm * 32 + mt * 16;
                a[mt][0] = curu[(r0 + grp) * GSTR + kk + tq];
                a[mt][1] = curu[(r0 + grp + 8) * GSTR + kk + tq];
                a[mt][2] = curu[(r0 + grp) * GSTR + kk + tq + 4];
                a[mt][3] = curu[(r0 + grp + 8) * GSTR + kk + tq + 4];
            }
            #pragma unroll
            for (int nt = 0; nt < 4; nt++) {
                int n0 = h * 64 + wn * 32 + nt * 8;
                uint32_t b0 = curu[(n0 + grp) * GSTR + kk + tq];
                uint32_t b1 = curu[(n0 + grp) * GSTR + kk + tq + 4];
                mma8(acc[0][nt], a[0], b0, b1);
                mma8(acc[1][nt], a[1], b0, b1);
            }
        }
        __syncthreads();
    }

    float* gp = g_Gpart + ((size_t)ch * NBAT + b) * NCH * NCH;
    #pragma unroll
    for (int mt = 0; mt < 2; mt++) {
        #pragma unroll
        for (int nt = 0; nt < 4; nt++) {
            int r = wm * 32 + mt * 16 + grp;
            int c = h * 64 + wn * 32 + nt * 8 + tq * 2;
            gp[r * NCH + c]           = acc[mt][nt][0];
            gp[r * NCH + c + 1]       = acc[mt][nt][1];
            gp[(r + 8) * NCH + c]     = acc[mt][nt][2];
            gp[(r + 8) * NCH + c + 1] = acc[mt][nt][3];
        }
    }
    if (h == 0) {
        rsum += __shfl_xor_sync(0xffffffffu, rsum, 1);
        if ((t & 1) == 0) g_spart[(ch * NBAT + b) * NCH + lrow] = rsum;
    }
}

__global__ void k_gred() {
    int j = blockIdx.x * 256 + threadIdx.x;
    float a = 0.f;
    #pragma unroll
    for (int ch = 0; ch < NCHUNK; ch++) a += g_Gpart[(size_t)ch * (NBAT * NCH * NCH) + j];
    g_G[j] = a;
    if (j < NBAT * NCH) {
        float t2 = 0.f;
        #pragma unroll
        for (int ch = 0; ch < NCHUNK; ch++) t2 += g_spart[ch * (NBAT * NCH) + j];
        g_s[j] = t2;
    }
}

// ---------------------------------------------------------------------------
// Fused small chain: one block per batch, all 128x128 matmuls via MMA in smem.
// ---------------------------------------------------------------------------
template<bool X2, class FA, class FB, class FE>
__device__ __forceinline__ void chain_mm(FA fa, FB fb, FE fe,
                                         int wm, int wn, int grp, int tq) {
    float acc[2][8][4];
    #pragma unroll
    for (int i = 0; i < 2; i++)
        #pragma unroll
        for (int j = 0; j < 8; j++)
            #pragma unroll
            for (int k = 0; k < 4; k++) acc[i][j][k] = 0.f;

    for (int kk = 0; kk < NCH; kk += 8) {
        uint32_t ah[2][4], al[2][4];
        #pragma unroll
        for (int mt = 0; mt < 2; mt++) {
            int r0 = wm * 32 + mt * 16;
            #pragma unroll
            for (int q = 0; q < 4; q++) {
                int rr = r0 + grp + ((q & 1) ? 8 : 0);
                int kc = kk + tq + ((q >> 1) ? 4 : 0);
                float f = fa(rr, kc);
                if constexpr (X2) tf32split(f, ah[mt][q], al[mt][q]);
                else ah[mt][q] = f2tf32(f);
            }
        }
        #pragma unroll
        for (int nt = 0; nt < 8; nt++) {
            int n = wn * 64 + nt * 8 + grp;
            float g0 = fb(n, kk + tq);
            float g1 = fb(n, kk + tq + 4);
            uint32_t bh0, bh1, bl0, bl1;
            if constexpr (X2) { tf32split(g0, bh0, bl0); tf32split(g1, bh1, bl1); }
            else { bh0 = f2tf32(g0); bh1 = f2tf32(g1); }
            mma8(acc[0][nt], ah[0], bh0, bh1);
            mma8(acc[1][nt], ah[1], bh0, bh1);
            if constexpr (X2) {
                mma8(acc[0][nt], al[0], bh0, bh1);
                mma8(acc[1][nt], al[1], bh0, bh1);
                mma8(acc[0][nt], ah[0], bl0, bl1);
                mma8(acc[1][nt], ah[1], bl0, bl1);
            }
        }
    }
    #pragma unroll
    for (int mt = 0; mt < 2; mt++)
        #pragma unroll
        for (int nt = 0; nt < 8; nt++) {
            int r = wm * 32 + mt * 16 + grp;
            int c = wn * 64 + nt * 8 + tq * 2;
            fe(r, c, acc[mt][nt][0], acc[mt][nt][1]);
            fe(r + 8, c, acc[mt][nt][2], acc[mt][nt][3]);
        }
}

__global__ __launch_bounds__(256) void k_chain(
    const float* __restrict__ Wq, const float* __restrict__ bq,
    const float* __restrict__ Wk, const float* __restrict__ bk,
    const float* __restrict__ Wv, const float* __restrict__ bv,
    const float* __restrict__ Wo, const float* __restrict__ bo,
    const float* __restrict__ gamma) {
    extern __shared__ float sm[];
    float* sA = sm;                 // 128 x LDSM
    float* sB = sm + NCH * LDSM;    // 128 x LDSM
    __shared__ float s_s[NCH], s_qs[NCH], s_ks[NCH], s_av[NCH];
    __shared__ float s_bq[NCH], s_bk[NCH], s_bv[NCH];

    int b = blockIdx.x, t = threadIdx.x;
    int lane = t & 31, wid = t >> 5;
    int grp = lane >> 2, tq = lane & 3;
    int wm = wid & 3, wn = wid >> 2;

    if (t < NCH) {
        s_s[t] = g_s[b * NCH + t];
        s_bq[t] = bq[t]; s_bk[t] = bk[t]; s_bv[t] = bv[t];
    }
    __syncthreads();

    // qs = Wq s, ks = Wk s
    {
        int d = t & 127;
        const float* W = (t < NCH) ? Wq : Wk;
        float a = 0.f;
        #pragma unroll 8
        for (int c = 0; c < NCH; c++) a += __ldg(&W[d * NCH + c]) * s_s[c];
        if (t < NCH) s_qs[d] = a; else s_ks[d] = a;
    }

    // G -> sA
    for (int i = t; i < NCH * 32; i += 256) {
        int r = i >> 5, c = (i & 31) << 2;
        *(float4*)(sA + r * LDSM + c) =
            *(const float4*)(g_G + (size_t)b * NCH * NCH + r * NCH + c);
    }
    __syncthreads();

    // T1 = Wq * G -> sB   (tf32x2)
    chain_mm<true>(
        [&](int r, int k) { return __ldg(&Wq[r * NCH + k]); },
        [&](int n, int k) { return sA[k * LDSM + n]; },
        [&](int r, int c, float v0, float v1) {
            sB[r * LDSM + c] = v0; sB[r * LDSM + c + 1] = v1;
        }, wm, wn, grp, tq);
    __syncthreads();

    // E = T1 * Wk^T + rank-1 -> sA   (tf32x2)
    chain_mm<true>(
        [&](int r, int k) { return sB[r * LDSM + k]; },
        [&](int n, int k) { return __ldg(&Wk[n * NCH + k]); },
        [&](int r, int c, float v0, float v1) {
            sA[r * LDSM + c] = v0 + s_qs[r] * s_bk[c]
                             + s_bq[r] * (s_ks[c] + (float)NTOK * s_bk[c]);
            sA[r * LDSM + c + 1] = v1 + s_qs[r] * s_bk[c + 1]
                             + s_bq[r] * (s_ks[c + 1] + (float)NTOK * s_bk[c + 1]);
        }, wm, wn, grp, tq);
    __syncthreads();

    // softmax rows of sA
    for (int r = wid; r < NCH; r += 8) {
        float4 v = *(float4*)(sA + r * LDSM + lane * 4);
        float m = fmaxf(fmaxf(v.x, v.y), fmaxf(v.z, v.w));
        #pragma unroll
        for (int o = 16; o; o >>= 1) m = fmaxf(m, __shfl_xor_sync(0xffffffffu, m, o));
        float e0 = __expf(v.x - m), e1 = __expf(v.y - m);
        float e2 = __expf(v.z - m), e3 = __expf(v.w - m);
        float s2 = e0 + e1 + e2 + e3;
        #pragma unroll
        for (int o = 16; o; o >>= 1) s2 += __shfl_xor_sync(0xffffffffu, s2, o);
        float inv = 1.f / s2;
        v.x = e0 * inv; v.y = e1 * inv; v.z = e2 * inv; v.w = e3 * inv;
        *(float4*)(sA + r * LDSM + lane * 4) = v;
    }
    __syncthreads();

    // av = A * bv
    if (t < NCH) {
        float a = 0.f;
        #pragma unroll 8
        for (int e = 0; e < NCH; e++) a += sA[t * LDSM + e] * s_bv[e];
        s_av[t] = a;
    }
    __syncthreads();

    // U = A * Wv -> sB  (tf32)
    chain_mm<false>(
        [&](int r, int k) { return sA[r * LDSM + k]; },
        [&](int n, int k) { return __ldg(&Wv[k * NCH + n]); },
        [&](int r, int c, float v0, float v1) {
            sB[r * LDSM + c] = v0; sB[r * LDSM + c + 1] = v1;
        }, wm, wn, grp, tq);
    __syncthreads();

    float gmv = __ldg(&gamma[0]);

    // M = gamma * Wo * U -> g_Mf (fragment-packed tf32)
    chain_mm<false>(
        [&](int r, int k) { return __ldg(&Wo[r * NCH + k]); },
        [&](int n, int k) { return sB[k * LDSM + n]; },
        [&](int r, int c, float v0, float v1) {
            g_Mf[b * 16384 + mf_index(r, c)]     = f2tf32(gmv * v0);
            g_Mf[b * 16384 + mf_index(r, c + 1)] = f2tf32(gmv * v1);
        }, wm, wn, grp, tq);

    // cvec = gamma * (Wo av + bo)
    if (t < NCH) {
        float a = 0.f;
        #pragma unroll 8
        for (int h = 0; h < NCH; h++) a += __ldg(&Wo[t * NCH + h]) * s_av[h];
        g_cvec[b * NCH + t] = gmv * (a + bo[t]);
    }
}

// ---------------------------------------------------------------------------
// Output: out = M * X + c 1^T + X
// 64-token tiles, 256 threads, 3 CTAs/SM (acc=32 regs). Quad-buffered X in
// smem, residual from smem, A-frags via pipelined LDG.128 from g_Mf.
// ---------------------------------------------------------------------------
__global__ __launch_bounds__(256, 3) void k_out(const float* __restrict__ x,
                                                float* __restrict__ out) {
    extern __shared__ float sx[];   // 4 stages x 32 x XST = 36864 B
    int b = blockIdx.y;
    int tok0 = blockIdx.x * TOKT;
    int t = threadIdx.x;
    int lane = t & 31, wid = t >> 5;
    int grp = lane >> 2, tq = lane & 3;
    int wm = wid & 3, wn = wid >> 2;   // wn in {0,1}: 32-token half

    const float* xb = x + (size_t)b * NCH * NTOK;
    const uint4* Mf = (const uint4*)g_Mf + (size_t)b * 4096;

    int lrow = t >> 3, loff = (t & 7) << 3;   // 32 rows x 64 floats per stage
    const float* gsrc = xb + (size_t)lrow * NTOK + tok0 + loff;
    #pragma unroll
    for (int s = 0; s < 4; s++) {
        uint32_t sd = (uint32_t)__cvta_generic_to_shared(sx + s * 32 * XST + lrow * XST + loff);
        const float* p = gsrc + (size_t)s * 32 * NTOK;
        cpa16(sd, p);
        cpa16(sd + 16, p + 4);
        asm volatile("cp.async.commit_group;");
    }

    // prefetch A-frags for kt = 0 (overlaps the stage-0 cp.async wait)
    uint4 nav0 = __ldg(&Mf[(0 * 8 + wm * 2 + 0) * 32 + lane]);
    uint4 nav1 = __ldg(&Mf[(0 * 8 + wm * 2 + 1) * 32 + lane]);

    float acc[2][4][4];
    #pragma unroll
    for (int i = 0; i < 2; i++)
        #pragma unroll
        for (int j = 0; j < 4; j++)
            #pragma unroll
            for (int k = 0; k < 4; k++) acc[i][j][k] = 0.f;

    #pragma unroll
    for (int s = 0; s < 4; s++) {
        if (s == 0)      asm volatile("cp.async.wait_group 3;");
        else if (s == 1) asm volatile("cp.async.wait_group 2;");
        else if (s == 2) asm volatile("cp.async.wait_group 1;");
        else             asm volatile("cp.async.wait_group 0;");
        __syncthreads();
        const uint32_t* curu = (const uint32_t*)(sx + s * 32 * XST);

        #pragma unroll
        for (int ks = 0; ks < 4; ks++) {
            int kk = ks * 8;
            int kt = s * 4 + ks;
            uint4 av0 = nav0, av1 = nav1;
            if (kt < 15) {   // prefetch next kt's fragments
                nav0 = __ldg(&Mf[((kt + 1) * 8 + wm * 2 + 0) * 32 + lane]);
                nav1 = __ldg(&Mf[((kt + 1) * 8 + wm * 2 + 1) * 32 + lane]);
            }
            uint32_t a0[4] = {av0.x, av0.y, av0.z, av0.w};
            uint32_t a1[4] = {av1.x, av1.y, av1.z, av1.w};
            #pragma unroll
            for (int nt = 0; nt < 4; nt++) {
                int n0 = wn * 32 + nt * 8;
                uint32_t b0 = curu[(kk + tq) * XST + n0 + grp];
                uint32_t b1 = curu[(kk + tq + 4) * XST + n0 + grp];
                mma8(acc[0][nt], a0, b0, b1);
                mma8(acc[1][nt], a1, b0, b1);
            }
        }
    }

    float* ob = out + (size_t)b * NCH * NTOK;
    #pragma unroll
    for (int mt = 0; mt < 2; mt++) {
        int r  = wm * 32 + mt * 16 + grp;
        int r1 = r + 8;
        float cv0 = g_cvec[b * NCH + r];
        float cv1 = g_cvec[b * NCH + r1];
        const float* res0 = sx + (r >> 5) * 32 * XST + (r & 31) * XST;
        const float* res1 = sx + (r1 >> 5) * 32 * XST + (r1 & 31) * XST;
        #pragma unroll
        for (int nt = 0; nt < 4; nt++) {
            int cl = wn * 32 + nt * 8 + tq * 2;
            int c = tok0 + cl;
            size_t i0 = (size_t)r * NTOK + c;
            size_t i1 = (size_t)r1 * NTOK + c;
            ob[i0]     = acc[mt][nt][0] + cv0 + res0[cl];
            ob[i0 + 1] = acc[mt][nt][1] + cv0 + res0[cl + 1];
            ob[i1]     = acc[mt][nt][2] + cv1 + res1[cl];
            ob[i1 + 1] = acc[mt][nt][3] + cv1 + res1[cl + 1];
        }
    }
}

extern "C" void kernel_launch(void* const* d_in, const int* in_sizes, int n_in,
                              void* d_out, int out_size) {
    const float* x  = (const float*)d_in[0];
    const float* Wq = (const float*)d_in[1];
    const float* bq = (const float*)d_in[2];
    const float* Wk = (const float*)d_in[3];
    const float* bk = (const float*)d_in[4];
    const float* Wv = (const float*)d_in[5];
    const float* bv = (const float*)d_in[6];
    const float* Wo = (const float*)d_in[7];
    const float* bo = (const float*)d_in[8];
    const float* gm = (const float*)d_in[9];
    float* out = (float*)d_out;

    const int gram_smem  = 2 * NCH * GSTR * (int)sizeof(float);          // 69632
    const int chain_smem = 2 * NCH * LDSM * (int)sizeof(float);          // 135168
    const int out_smem   = 4 * 32 * XST * (int)sizeof(float);            // 36864
    cudaFuncSetAttribute(k_gram,  cudaFuncAttributeMaxDynamicSharedMemorySize, gram_smem);
    cudaFuncSetAttribute(k_chain, cudaFuncAttributeMaxDynamicSharedMemorySize, chain_smem);
    cudaFuncSetAttribute(k_out,   cudaFuncAttributeMaxDynamicSharedMemorySize, out_smem);

    k_gram<<<dim3(NCHUNK, 2, NBAT), 256, gram_smem>>>(x);
    k_gred<<<(NBAT * NCH * NCH) / 256, 256>>>();
    k_chain<<<NBAT, 256, chain_smem>>>(Wq, bq, Wk, bk, Wv, bv, Wo, bo, gm);
    k_out<<<dim3(NTOK / TOKT, NBAT), 256, out_smem>>>(x, out);
}

// round 13
// speedup vs baseline: 1.1700x; 1.1700x over previous
#include <cuda_runtime.h>
#include <cstdint>
#include <cstddef>

// Channel self-attention via Gram restructuring:
//   G_b = X X^T, s_b = X 1
//   E = Wq G Wk^T + (Wq s) bk^T + bq (Wk s)^T + N bq bk^T ; A = softmax(E)
//   M = gamma * Wo (A Wv) ; c = gamma * (Wo A bv + bo)
//   out = M X + c 1^T + X
//
// Inner GEMM loops feed raw fp32 bits to tf32 mma (HW truncates mantissa).
// k_gram: 128x128 tile/CTA, 2 CTAs/SM (R11 config — measured best).
// k_out: 64-token tiles, acc=32 regs, 3 CTAs/SM (R12 config — measured best).
// E-path keeps tf32x2 rna splits.

#define NTOK 36864
#define NCH 128
#define NBAT 8
#define NCHUNK 36
#define CHUNK 1024
#define GW 64     /* gram stage width (cols) */
#define GSTR 68   /* gram smem stride; 68%32==4 -> conflict-free */
#define LDSM 132
#define TOKT 64
#define XST 72    /* X stage stride; 72%32==8 -> conflict-free B frags */

__device__ float g_Gpart[NCHUNK * NBAT * NCH * NCH];
__device__ float g_spart[NCHUNK * NBAT * NCH];
__device__ float g_G[NBAT * NCH * NCH];
__device__ float g_s[NBAT * NCH];
__device__ uint32_t g_Mf[NBAT * 16384];   // M in tf32, mma-fragment-packed
__device__ float g_cvec[NBAT * NCH];

__device__ __forceinline__ uint32_t f2tf32(float f) {
    uint32_t u;
    asm("cvt.rna.tf32.f32 %0, %1;" : "=r"(u) : "f"(f));
    return u;
}

__device__ __forceinline__ void tf32split(float f, uint32_t& hi, uint32_t& lo) {
    uint32_t h;
    asm("cvt.rna.tf32.f32 %0, %1;" : "=r"(h) : "f"(f));
    float fh = __uint_as_float(h);
    float r = f - fh;
    uint32_t l;
    asm("cvt.rna.tf32.f32 %0, %1;" : "=r"(l) : "f"(r));
    hi = h; lo = l;
}

__device__ __forceinline__ void mma8(float* d, const uint32_t* a, uint32_t b0, uint32_t b1) {
    asm volatile(
        "mma.sync.aligned.m16n8k8.row.col.f32.tf32.tf32.f32 "
        "{%0,%1,%2,%3},{%4,%5,%6,%7},{%8,%9},{%0,%1,%2,%3};"
        : "+f"(d[0]), "+f"(d[1]), "+f"(d[2]), "+f"(d[3])
        : "r"(a[0]), "r"(a[1]), "r"(a[2]), "r"(a[3]), "r"(b0), "r"(b1));
}

__device__ __forceinline__ void cpa16(uint32_t dst, const void* src) {
    asm volatile("cp.async.cg.shared.global [%0],[%1],16;" :: "r"(dst), "l"(src));
}

// Fragment-packed M index: element (r, c) of the 128x128 matrix ->
// [kt(16)][mtile(8)][lane(32)][q(4)], lane = 4*grp+tq, q = qhi*2+qlo.
__device__ __forceinline__ int mf_index(int r, int c) {
    int kt = c >> 3, w = c & 7, qhi = w >> 2, tq = w & 3;
    int mtile = r >> 4, rr = r & 15, qlo = rr >> 3, grp = rr & 7;
    return ((kt * 8 + mtile) * 32 + grp * 4 + tq) * 4 + qhi * 2 + qlo;
}

// ---------------------------------------------------------------------------
// Gram: per (chunk, batch) block computes 128x128 partial X X^T over 1024 cols
// (16 stages of 64, double-buffered). Raw fp32 operands (HW tf32 truncation).
// Deterministic. 2 CTAs/SM. [R11 config — measured best]
// ---------------------------------------------------------------------------
__global__ __launch_bounds__(256, 2) void k_gram(const float* __restrict__ x) {
    extern __shared__ float sb[];   // 2 x 128 x GSTR = 69632 B
    int b = blockIdx.y, ch = blockIdx.x;
    int t = threadIdx.x;
    int lrow = t >> 1, lcol = (t & 1) << 5;
    int lane = t & 31, wid = t >> 5;
    int grp = lane >> 2, tq = lane & 3;
    int wm = wid & 3, wn = wid >> 2;

    const float* gsrc = x + (size_t)b * NCH * NTOK + (size_t)lrow * NTOK
                          + (size_t)ch * CHUNK + lcol;
    uint32_t sd0 = (uint32_t)__cvta_generic_to_shared(sb + lrow * GSTR + lcol);
    uint32_t sd1 = (uint32_t)__cvta_generic_to_shared(sb + NCH * GSTR + lrow * GSTR + lcol);

    float acc[2][8][4];
    #pragma unroll
    for (int i = 0; i < 2; i++)
        #pragma unroll
        for (int j = 0; j < 8; j++)
            #pragma unroll
            for (int k = 0; k < 4; k++) acc[i][j][k] = 0.f;
    float rsum = 0.f;

    #pragma unroll
    for (int j = 0; j < 8; j++) cpa16(sd0 + j * 16, gsrc + j * 4);
    asm volatile("cp.async.commit_group;");

    const int NST = CHUNK / GW;  // 16
    for (int s = 0; s < NST; s++) {
        if (s + 1 < NST) {
            uint32_t dd = ((s + 1) & 1) ? sd1 : sd0;
            const float* p = gsrc + (s + 1) * GW;
            #pragma unroll
            for (int j = 0; j < 8; j++) cpa16(dd + j * 16, p + j * 4);
            asm volatile("cp.async.commit_group;");
            asm volatile("cp.async.wait_group 1;");
        } else {
            asm volatile("cp.async.wait_group 0;");
        }
        __syncthreads();
        const float* cur = sb + (s & 1) * NCH * GSTR;
        const uint32_t* curu = (const uint32_t*)cur;

        {
            const float4* rp4 = (const float4*)(cur + lrow * GSTR + lcol);
            #pragma unroll
            for (int i = 0; i < 8; i++) {
                float4 v = rp4[i];
                rsum += v.x + v.y + v.z + v.w;
            }
        }

        #pragma unroll
        for (int ks = 0; ks < 8; ks++) {
            int kk = ks * 8;
            uint32_t a[2][4];
            #pragma unroll
            for (int mt = 0; mt < 2; mt++) {
                int r0 = wm * 32 + mt * 16;
                a[mt][0] = curu[(r0 + grp) * GSTR + kk + tq];
                a[mt][1] = curu[(r0 + grp + 8) * GSTR + kk + tq];
                a[mt][2] = curu[(r0 + grp) * GSTR + kk + tq + 4];
                a[mt][3] = curu[(r0 + grp + 8) * GSTR + kk + tq + 4];
            }
            #pragma unroll
            for (int nt = 0; nt < 8; nt++) {
                int n0 = wn * 64 + nt * 8;
                uint32_t b0 = curu[(n0 + grp) * GSTR + kk + tq];
                uint32_t b1 = curu[(n0 + grp) * GSTR + kk + tq + 4];
                mma8(acc[0][nt], a[0], b0, b1);
                mma8(acc[1][nt], a[1], b0, b1);
            }
        }
        __syncthreads();
    }

    float* gp = g_Gpart + ((size_t)ch * NBAT + b) * NCH * NCH;
    #pragma unroll
    for (int mt = 0; mt < 2; mt++) {
        #pragma unroll
        for (int nt = 0; nt < 8; nt++) {
            int r = wm * 32 + mt * 16 + grp;
            int c = wn * 64 + nt * 8 + tq * 2;
            gp[r * NCH + c]           = acc[mt][nt][0];
            gp[r * NCH + c + 1]       = acc[mt][nt][1];
            gp[(r + 8) * NCH + c]     = acc[mt][nt][2];
            gp[(r + 8) * NCH + c + 1] = acc[mt][nt][3];
        }
    }
    rsum += __shfl_xor_sync(0xffffffffu, rsum, 1);
    if ((t & 1) == 0) g_spart[(ch * NBAT + b) * NCH + lrow] = rsum;
}

__global__ void k_gred() {
    int j = blockIdx.x * 256 + threadIdx.x;
    float a = 0.f;
    #pragma unroll
    for (int ch = 0; ch < NCHUNK; ch++) a += g_Gpart[(size_t)ch * (NBAT * NCH * NCH) + j];
    g_G[j] = a;
    if (j < NBAT * NCH) {
        float t2 = 0.f;
        #pragma unroll
        for (int ch = 0; ch < NCHUNK; ch++) t2 += g_spart[ch * (NBAT * NCH) + j];
        g_s[j] = t2;
    }
}

// ---------------------------------------------------------------------------
// Fused small chain: one block per batch, all 128x128 matmuls via MMA in smem.
// ---------------------------------------------------------------------------
template<bool X2, class FA, class FB, class FE>
__device__ __forceinline__ void chain_mm(FA fa, FB fb, FE fe,
                                         int wm, int wn, int grp, int tq) {
    float acc[2][8][4];
    #pragma unroll
    for (int i = 0; i < 2; i++)
        #pragma unroll
        for (int j = 0; j < 8; j++)
            #pragma unroll
            for (int k = 0; k < 4; k++) acc[i][j][k] = 0.f;

    for (int kk = 0; kk < NCH; kk += 8) {
        uint32_t ah[2][4], al[2][4];
        #pragma unroll
        for (int mt = 0; mt < 2; mt++) {
            int r0 = wm * 32 + mt * 16;
            #pragma unroll
            for (int q = 0; q < 4; q++) {
                int rr = r0 + grp + ((q & 1) ? 8 : 0);
                int kc = kk + tq + ((q >> 1) ? 4 : 0);
                float f = fa(rr, kc);
                if constexpr (X2) tf32split(f, ah[mt][q], al[mt][q]);
                else ah[mt][q] = f2tf32(f);
            }
        }
        #pragma unroll
        for (int nt = 0; nt < 8; nt++) {
            int n = wn * 64 + nt * 8 + grp;
            float g0 = fb(n, kk + tq);
            float g1 = fb(n, kk + tq + 4);
            uint32_t bh0, bh1, bl0, bl1;
            if constexpr (X2) { tf32split(g0, bh0, bl0); tf32split(g1, bh1, bl1); }
            else { bh0 = f2tf32(g0); bh1 = f2tf32(g1); }
            mma8(acc[0][nt], ah[0], bh0, bh1);
            mma8(acc[1][nt], ah[1], bh0, bh1);
            if constexpr (X2) {
                mma8(acc[0][nt], al[0], bh0, bh1);
                mma8(acc[1][nt], al[1], bh0, bh1);
                mma8(acc[0][nt], ah[0], bl0, bl1);
                mma8(acc[1][nt], ah[1], bl0, bl1);
            }
        }
    }
    #pragma unroll
    for (int mt = 0; mt < 2; mt++)
        #pragma unroll
        for (int nt = 0; nt < 8; nt++) {
            int r = wm * 32 + mt * 16 + grp;
            int c = wn * 64 + nt * 8 + tq * 2;
            fe(r, c, acc[mt][nt][0], acc[mt][nt][1]);
            fe(r + 8, c, acc[mt][nt][2], acc[mt][nt][3]);
        }
}

__global__ __launch_bounds__(256) void k_chain(
    const float* __restrict__ Wq, const float* __restrict__ bq,
    const float* __restrict__ Wk, const float* __restrict__ bk,
    const float* __restrict__ Wv, const float* __restrict__ bv,
    const float* __restrict__ Wo, const float* __restrict__ bo,
    const float* __restrict__ gamma) {
    extern __shared__ float sm[];
    float* sA = sm;                 // 128 x LDSM
    float* sB = sm + NCH * LDSM;    // 128 x LDSM
    __shared__ float s_s[NCH], s_qs[NCH], s_ks[NCH], s_av[NCH];
    __shared__ float s_bq[NCH], s_bk[NCH], s_bv[NCH];

    int b = blockIdx.x, t = threadIdx.x;
    int lane = t & 31, wid = t >> 5;
    int grp = lane >> 2, tq = lane & 3;
    int wm = wid & 3, wn = wid >> 2;

    if (t < NCH) {
        s_s[t] = g_s[b * NCH + t];
        s_bq[t] = bq[t]; s_bk[t] = bk[t]; s_bv[t] = bv[t];
    }
    __syncthreads();

    // qs = Wq s, ks = Wk s
    {
        int d = t & 127;
        const float* W = (t < NCH) ? Wq : Wk;
        float a = 0.f;
        #pragma unroll 8
        for (int c = 0; c < NCH; c++) a += __ldg(&W[d * NCH + c]) * s_s[c];
        if (t < NCH) s_qs[d] = a; else s_ks[d] = a;
    }

    // G -> sA
    for (int i = t; i < NCH * 32; i += 256) {
        int r = i >> 5, c = (i & 31) << 2;
        *(float4*)(sA + r * LDSM + c) =
            *(const float4*)(g_G + (size_t)b * NCH * NCH + r * NCH + c);
    }
    __syncthreads();

    // T1 = Wq * G -> sB   (tf32x2)
    chain_mm<true>(
        [&](int r, int k) { return __ldg(&Wq[r * NCH + k]); },
        [&](int n, int k) { return sA[k * LDSM + n]; },
        [&](int r, int c, float v0, float v1) {
            sB[r * LDSM + c] = v0; sB[r * LDSM + c + 1] = v1;
        }, wm, wn, grp, tq);
    __syncthreads();

    // E = T1 * Wk^T + rank-1 -> sA   (tf32x2)
    chain_mm<true>(
        [&](int r, int k) { return sB[r * LDSM + k]; },
        [&](int n, int k) { return __ldg(&Wk[n * NCH + k]); },
        [&](int r, int c, float v0, float v1) {
            sA[r * LDSM + c] = v0 + s_qs[r] * s_bk[c]
                             + s_bq[r] * (s_ks[c] + (float)NTOK * s_bk[c]);
            sA[r * LDSM + c + 1] = v1 + s_qs[r] * s_bk[c + 1]
                             + s_bq[r] * (s_ks[c + 1] + (float)NTOK * s_bk[c + 1]);
        }, wm, wn, grp, tq);
    __syncthreads();

    // softmax rows of sA
    for (int r = wid; r < NCH; r += 8) {
        float4 v = *(float4*)(sA + r * LDSM + lane * 4);
        float m = fmaxf(fmaxf(v.x, v.y), fmaxf(v.z, v.w));
        #pragma unroll
        for (int o = 16; o; o >>= 1) m = fmaxf(m, __shfl_xor_sync(0xffffffffu, m, o));
        float e0 = __expf(v.x - m), e1 = __expf(v.y - m);
        float e2 = __expf(v.z - m), e3 = __expf(v.w - m);
        float s2 = e0 + e1 + e2 + e3;
        #pragma unroll
        for (int o = 16; o; o >>= 1) s2 += __shfl_xor_sync(0xffffffffu, s2, o);
        float inv = 1.f / s2;
        v.x = e0 * inv; v.y = e1 * inv; v.z = e2 * inv; v.w = e3 * inv;
        *(float4*)(sA + r * LDSM + lane * 4) = v;
    }
    __syncthreads();

    // av = A * bv
    if (t < NCH) {
        float a = 0.f;
        #pragma unroll 8
        for (int e = 0; e < NCH; e++) a += sA[t * LDSM + e] * s_bv[e];
        s_av[t] = a;
    }
    __syncthreads();

    // U = A * Wv -> sB  (tf32)
    chain_mm<false>(
        [&](int r, int k) { return sA[r * LDSM + k]; },
        [&](int n, int k) { return __ldg(&Wv[k * NCH + n]); },
        [&](int r, int c, float v0, float v1) {
            sB[r * LDSM + c] = v0; sB[r * LDSM + c + 1] = v1;
        }, wm, wn, grp, tq);
    __syncthreads();

    float gmv = __ldg(&gamma[0]);

    // M = gamma * Wo * U -> g_Mf (fragment-packed tf32)
    chain_mm<false>(
        [&](int r, int k) { return __ldg(&Wo[r * NCH + k]); },
        [&](int n, int k) { return sB[k * LDSM + n]; },
        [&](int r, int c, float v0, float v1) {
            g_Mf[b * 16384 + mf_index(r, c)]     = f2tf32(gmv * v0);
            g_Mf[b * 16384 + mf_index(r, c + 1)] = f2tf32(gmv * v1);
        }, wm, wn, grp, tq);

    // cvec = gamma * (Wo av + bo)
    if (t < NCH) {
        float a = 0.f;
        #pragma unroll 8
        for (int h = 0; h < NCH; h++) a += __ldg(&Wo[t * NCH + h]) * s_av[h];
        g_cvec[b * NCH + t] = gmv * (a + bo[t]);
    }
}

// ---------------------------------------------------------------------------
// Output: out = M * X + c 1^T + X
// 64-token tiles, 256 threads, 3 CTAs/SM (acc=32 regs). Quad-buffered X in
// smem, residual from smem, A-frags via pipelined LDG.128 from g_Mf.
// [R12 config — measured best]
// ---------------------------------------------------------------------------
__global__ __launch_bounds__(256, 3) void k_out(const float* __restrict__ x,
                                                float* __restrict__ out) {
    extern __shared__ float sx[];   // 4 stages x 32 x XST = 36864 B
    int b = blockIdx.y;
    int tok0 = blockIdx.x * TOKT;
    int t = threadIdx.x;
    int lane = t & 31, wid = t >> 5;
    int grp = lane >> 2, tq = lane & 3;
    int wm = wid & 3, wn = wid >> 2;   // wn in {0,1}: 32-token half

    const float* xb = x + (size_t)b * NCH * NTOK;
    const uint4* Mf = (const uint4*)g_Mf + (size_t)b * 4096;

    int lrow = t >> 3, loff = (t & 7) << 3;   // 32 rows x 64 floats per stage
    const float* gsrc = xb + (size_t)lrow * NTOK + tok0 + loff;
    #pragma unroll
    for (int s = 0; s < 4; s++) {
        uint32_t sd = (uint32_t)__cvta_generic_to_shared(sx + s * 32 * XST + lrow * XST + loff);
        const float* p = gsrc + (size_t)s * 32 * NTOK;
        cpa16(sd, p);
        cpa16(sd + 16, p + 4);
        asm volatile("cp.async.commit_group;");
    }

    // prefetch A-frags for kt = 0 (overlaps the stage-0 cp.async wait)
    uint4 nav0 = __ldg(&Mf[(0 * 8 + wm * 2 + 0) * 32 + lane]);
    uint4 nav1 = __ldg(&Mf[(0 * 8 + wm * 2 + 1) * 32 + lane]);

    float acc[2][4][4];
    #pragma unroll
    for (int i = 0; i < 2; i++)
        #pragma unroll
        for (int j = 0; j < 4; j++)
            #pragma unroll
            for (int k = 0; k < 4; k++) acc[i][j][k] = 0.f;

    #pragma unroll
    for (int s = 0; s < 4; s++) {
        if (s == 0)      asm volatile("cp.async.wait_group 3;");
        else if (s == 1) asm volatile("cp.async.wait_group 2;");
        else if (s == 2) asm volatile("cp.async.wait_group 1;");
        else             asm volatile("cp.async.wait_group 0;");
        __syncthreads();
        const uint32_t* curu = (const uint32_t*)(sx + s * 32 * XST);

        #pragma unroll
        for (int ks = 0; ks < 4; ks++) {
            int kk = ks * 8;
            int kt = s * 4 + ks;
            uint4 av0 = nav0, av1 = nav1;
            if (kt < 15) {   // prefetch next kt's fragments
                nav0 = __ldg(&Mf[((kt + 1) * 8 + wm * 2 + 0) * 32 + lane]);
                nav1 = __ldg(&Mf[((kt + 1) * 8 + wm * 2 + 1) * 32 + lane]);
            }
            uint32_t a0[4] = {av0.x, av0.y, av0.z, av0.w};
            uint32_t a1[4] = {av1.x, av1.y, av1.z, av1.w};
            #pragma unroll
            for (int nt = 0; nt < 4; nt++) {
                int n0 = wn * 32 + nt * 8;
                uint32_t b0 = curu[(kk + tq) * XST + n0 + grp];
                uint32_t b1 = curu[(kk + tq + 4) * XST + n0 + grp];
                mma8(acc[0][nt], a0, b0, b1);
                mma8(acc[1][nt], a1, b0, b1);
            }
        }
    }

    float* ob = out + (size_t)b * NCH * NTOK;
    #pragma unroll
    for (int mt = 0; mt < 2; mt++) {
        int r  = wm * 32 + mt * 16 + grp;
        int r1 = r + 8;
        float cv0 = g_cvec[b * NCH + r];
        float cv1 = g_cvec[b * NCH + r1];
        const float* res0 = sx + (r >> 5) * 32 * XST + (r & 31) * XST;
        const float* res1 = sx + (r1 >> 5) * 32 * XST + (r1 & 31) * XST;
        #pragma unroll
        for (int nt = 0; nt < 4; nt++) {
            int cl = wn * 32 + nt * 8 + tq * 2;
            int c = tok0 + cl;
            size_t i0 = (size_t)r * NTOK + c;
            size_t i1 = (size_t)r1 * NTOK + c;
            ob[i0]     = acc[mt][nt][0] + cv0 + res0[cl];
            ob[i0 + 1] = acc[mt][nt][1] + cv0 + res0[cl + 1];
            ob[i1]     = acc[mt][nt][2] + cv1 + res1[cl];
            ob[i1 + 1] = acc[mt][nt][3] + cv1 + res1[cl + 1];
        }
    }
}

extern "C" void kernel_launch(void* const* d_in, const int* in_sizes, int n_in,
                              void* d_out, int out_size) {
    const float* x  = (const float*)d_in[0];
    const float* Wq = (const float*)d_in[1];
    const float* bq = (const float*)d_in[2];
    const float* Wk = (const float*)d_in[3];
    const float* bk = (const float*)d_in[4];
    const float* Wv = (const float*)d_in[5];
    const float* bv = (const float*)d_in[6];
    const float* Wo = (const float*)d_in[7];
    const float* bo = (const float*)d_in[8];
    const float* gm = (const float*)d_in[9];
    float* out = (float*)d_out;

    const int gram_smem  = 2 * NCH * GSTR * (int)sizeof(float);          // 69632
    const int chain_smem = 2 * NCH * LDSM * (int)sizeof(float);          // 135168
    const int out_smem   = 4 * 32 * XST * (int)sizeof(float);            // 36864
    cudaFuncSetAttribute(k_gram,  cudaFuncAttributeMaxDynamicSharedMemorySize, gram_smem);
    cudaFuncSetAttribute(k_chain, cudaFuncAttributeMaxDynamicSharedMemorySize, chain_smem);
    cudaFuncSetAttribute(k_out,   cudaFuncAttributeMaxDynamicSharedMemorySize, out_smem);

    k_gram<<<dim3(NCHUNK, NBAT), 256, gram_smem>>>(x);
    k_gred<<<(NBAT * NCH * NCH) / 256, 256>>>();
    k_chain<<<NBAT, 256, chain_smem>>>(Wq, bq, Wk, bk, Wv, bv, Wo, bo, gm);
    k_out<<<dim3(NTOK / TOKT, NBAT), 256, out_smem>>>(x, out);
}

// round 14
// speedup vs baseline: 1.2945x; 1.1064x over previous
#include <cuda_runtime.h>
#include <cstdint>
#include <cstddef>

// Channel self-attention via Gram restructuring:
//   G_b = X X^T, s_b = X 1
//   E = Wq G Wk^T + (Wq s) bk^T + bq (Wk s)^T + N bq bk^T ; A = softmax(E)
//   M = gamma * Wo (A Wv) ; c = gamma * (Wo A bv + bo)
//   out = M X + c 1^T + X
//
// Big GEMMs use bf16 mma.m16n8k16 (half the mma/LDS per FLOP vs tf32 k8).
// X staged fp32 via cp.async (residual + row sums stay fp32-exact), converted
// once per stage into a compact conflict-free bf16 smem buffer. M is packed
// bf16x2 in mma-fragment order by k_chain. E-path keeps tf32x2 rna splits.

#define NTOK 36864
#define NCH 128
#define NBAT 8
#define NCHUNK 36
#define CHUNK 1024
#define GW 64     /* gram stage width (cols) */
#define GSTR 68   /* gram fp32 stage stride (floats); 68%32==4 */
#define BSTR 36   /* gram bf16 buf stride (b32 words); 36%32==4 -> conflict-free */
#define LDSM 132
#define TOKT 64
#define XST 72    /* k_out fp32 stage stride (floats); 72%32==8 */
#define BST2 20   /* k_out bf16 buf stride (b32 words, token-major); 20%32 */

__device__ float g_Gpart[NCHUNK * NBAT * NCH * NCH];
__device__ float g_spart[NCHUNK * NBAT * NCH];
__device__ float g_G[NBAT * NCH * NCH];
__device__ float g_s[NBAT * NCH];
__device__ uint32_t g_Mh[NBAT * 8192];   // M as bf16x2, mma-fragment-packed (32 KB/batch)
__device__ float g_cvec[NBAT * NCH];

__device__ __forceinline__ uint32_t f2tf32(float f) {
    uint32_t u;
    asm("cvt.rna.tf32.f32 %0, %1;" : "=r"(u) : "f"(f));
    return u;
}

__device__ __forceinline__ void tf32split(float f, uint32_t& hi, uint32_t& lo) {
    uint32_t h;
    asm("cvt.rna.tf32.f32 %0, %1;" : "=r"(h) : "f"(f));
    float fh = __uint_as_float(h);
    float r = f - fh;
    uint32_t l;
    asm("cvt.rna.tf32.f32 %0, %1;" : "=r"(l) : "f"(r));
    hi = h; lo = l;
}

// pack two fp32 into bf16x2 (lo = first/even element)
__device__ __forceinline__ uint32_t packbf16(float lo, float hi) {
    uint32_t r;
    asm("cvt.rn.bf16x2.f32 %0, %1, %2;" : "=r"(r) : "f"(hi), "f"(lo));
    return r;
}

__device__ __forceinline__ void mma8(float* d, const uint32_t* a, uint32_t b0, uint32_t b1) {
    asm volatile(
        "mma.sync.aligned.m16n8k8.row.col.f32.tf32.tf32.f32 "
        "{%0,%1,%2,%3},{%4,%5,%6,%7},{%8,%9},{%0,%1,%2,%3};"
        : "+f"(d[0]), "+f"(d[1]), "+f"(d[2]), "+f"(d[3])
        : "r"(a[0]), "r"(a[1]), "r"(a[2]), "r"(a[3]), "r"(b0), "r"(b1));
}

__device__ __forceinline__ void mma16(float* d, const uint32_t* a, uint32_t b0, uint32_t b1) {
    asm volatile(
        "mma.sync.aligned.m16n8k16.row.col.f32.bf16.bf16.f32 "
        "{%0,%1,%2,%3},{%4,%5,%6,%7},{%8,%9},{%0,%1,%2,%3};"
        : "+f"(d[0]), "+f"(d[1]), "+f"(d[2]), "+f"(d[3])
        : "r"(a[0]), "r"(a[1]), "r"(a[2]), "r"(a[3]), "r"(b0), "r"(b1));
}

__device__ __forceinline__ void cpa16(uint32_t dst, const void* src) {
    asm volatile("cp.async.cg.shared.global [%0],[%1],16;" :: "r"(dst), "l"(src));
}

// ---------------------------------------------------------------------------
// Gram: per (chunk, batch) block computes 128x128 partial X X^T over 1024 cols
// (16 stages of 64). fp32 cp.async staging (double-buffered), per-stage
// convert to bf16 buffer, mma.m16n8k16. Deterministic. 2 CTAs/SM.
// ---------------------------------------------------------------------------
__global__ __launch_bounds__(256, 2) void k_gram(const float* __restrict__ x) {
    extern __shared__ float sb[];
    // [0, 2*128*GSTR) fp32 stages; then 128*BSTR b32 words bf16 buffer
    uint32_t* sh = (uint32_t*)(sb + 2 * NCH * GSTR);

    int b = blockIdx.y, ch = blockIdx.x;
    int t = threadIdx.x;
    int lrow = t >> 1, lcol = (t & 1) << 5;
    int lane = t & 31, wid = t >> 5;
    int grp = lane >> 2, tq = lane & 3;
    int wm = wid & 3, wn = wid >> 2;

    const float* gsrc = x + (size_t)b * NCH * NTOK + (size_t)lrow * NTOK
                          + (size_t)ch * CHUNK + lcol;
    uint32_t sd0 = (uint32_t)__cvta_generic_to_shared(sb + lrow * GSTR + lcol);
    uint32_t sd1 = (uint32_t)__cvta_generic_to_shared(sb + NCH * GSTR + lrow * GSTR + lcol);

    float acc[2][8][4];
    #pragma unroll
    for (int i = 0; i < 2; i++)
        #pragma unroll
        for (int j = 0; j < 8; j++)
            #pragma unroll
            for (int k = 0; k < 4; k++) acc[i][j][k] = 0.f;
    float rsum = 0.f;

    #pragma unroll
    for (int j = 0; j < 8; j++) cpa16(sd0 + j * 16, gsrc + j * 4);
    asm volatile("cp.async.commit_group;");

    const int NST = CHUNK / GW;  // 16
    for (int s = 0; s < NST; s++) {
        if (s + 1 < NST) {
            uint32_t dd = ((s + 1) & 1) ? sd1 : sd0;
            const float* p = gsrc + (s + 1) * GW;
            #pragma unroll
            for (int j = 0; j < 8; j++) cpa16(dd + j * 16, p + j * 4);
            asm volatile("cp.async.commit_group;");
            asm volatile("cp.async.wait_group 1;");
        } else {
            asm volatile("cp.async.wait_group 0;");
        }
        __syncthreads();   // fp32 stage s ready; all warps done with prior mma
        const float* cur = sb + (s & 1) * NCH * GSTR;

        // convert stage s -> bf16 buffer (+ row-sum accumulation, fp32 exact)
        {
            const float4* rp4 = (const float4*)(cur + lrow * GSTR + lcol);
            uint32_t w[16];
            #pragma unroll
            for (int i = 0; i < 8; i++) {
                float4 v = rp4[i];
                rsum += v.x + v.y + v.z + v.w;
                w[2 * i]     = packbf16(v.x, v.y);
                w[2 * i + 1] = packbf16(v.z, v.w);
            }
            uint4* dst = (uint4*)(sh + lrow * BSTR + ((t & 1) << 4));
            #pragma unroll
            for (int j = 0; j < 4; j++)
                dst[j] = make_uint4(w[4 * j], w[4 * j + 1], w[4 * j + 2], w[4 * j + 3]);
        }
        __syncthreads();   // bf16 buffer ready

        #pragma unroll
        for (int kt = 0; kt < 4; kt++) {   // 4 ktiles of K=16
            int kb = kt * 8;
            uint32_t a[2][4];
            #pragma unroll
            for (int mt = 0; mt < 2; mt++) {
                int r0 = wm * 32 + mt * 16;
                a[mt][0] = sh[(r0 + grp) * BSTR + kb + tq];
                a[mt][1] = sh[(r0 + grp + 8) * BSTR + kb + tq];
                a[mt][2] = sh[(r0 + grp) * BSTR + kb + tq + 4];
                a[mt][3] = sh[(r0 + grp + 8) * BSTR + kb + tq + 4];
            }
            #pragma unroll
            for (int nt = 0; nt < 8; nt++) {
                int n0 = wn * 64 + nt * 8;
                uint32_t b0 = sh[(n0 + grp) * BSTR + kb + tq];
                uint32_t b1 = sh[(n0 + grp) * BSTR + kb + tq + 4];
                mma16(acc[0][nt], a[0], b0, b1);
                mma16(acc[1][nt], a[1], b0, b1);
            }
        }
        // next stage's top barrier fences bf16-buffer reuse
    }

    float* gp = g_Gpart + ((size_t)ch * NBAT + b) * NCH * NCH;
    #pragma unroll
    for (int mt = 0; mt < 2; mt++) {
        #pragma unroll
        for (int nt = 0; nt < 8; nt++) {
            int r = wm * 32 + mt * 16 + grp;
            int c = wn * 64 + nt * 8 + tq * 2;
            gp[r * NCH + c]           = acc[mt][nt][0];
            gp[r * NCH + c + 1]       = acc[mt][nt][1];
            gp[(r + 8) * NCH + c]     = acc[mt][nt][2];
            gp[(r + 8) * NCH + c + 1] = acc[mt][nt][3];
        }
    }
    rsum += __shfl_xor_sync(0xffffffffu, rsum, 1);
    if ((t & 1) == 0) g_spart[(ch * NBAT + b) * NCH + lrow] = rsum;
}

__global__ void k_gred() {
    int j = blockIdx.x * 256 + threadIdx.x;
    float a = 0.f;
    #pragma unroll
    for (int ch = 0; ch < NCHUNK; ch++) a += g_Gpart[(size_t)ch * (NBAT * NCH * NCH) + j];
    g_G[j] = a;
    if (j < NBAT * NCH) {
        float t2 = 0.f;
        #pragma unroll
        for (int ch = 0; ch < NCHUNK; ch++) t2 += g_spart[ch * (NBAT * NCH) + j];
        g_s[j] = t2;
    }
}

// ---------------------------------------------------------------------------
// Fused small chain: one block per batch, all 128x128 matmuls via MMA in smem.
// ---------------------------------------------------------------------------
template<bool X2, class FA, class FB, class FE>
__device__ __forceinline__ void chain_mm(FA fa, FB fb, FE fe,
                                         int wm, int wn, int grp, int tq) {
    float acc[2][8][4];
    #pragma unroll
    for (int i = 0; i < 2; i++)
        #pragma unroll
        for (int j = 0; j < 8; j++)
            #pragma unroll
            for (int k = 0; k < 4; k++) acc[i][j][k] = 0.f;

    for (int kk = 0; kk < NCH; kk += 8) {
        uint32_t ah[2][4], al[2][4];
        #pragma unroll
        for (int mt = 0; mt < 2; mt++) {
            int r0 = wm * 32 + mt * 16;
            #pragma unroll
            for (int q = 0; q < 4; q++) {
                int rr = r0 + grp + ((q & 1) ? 8 : 0);
                int kc = kk + tq + ((q >> 1) ? 4 : 0);
                float f = fa(rr, kc);
                if constexpr (X2) tf32split(f, ah[mt][q], al[mt][q]);
                else ah[mt][q] = f2tf32(f);
            }
        }
        #pragma unroll
        for (int nt = 0; nt < 8; nt++) {
            int n = wn * 64 + nt * 8 + grp;
            float g0 = fb(n, kk + tq);
            float g1 = fb(n, kk + tq + 4);
            uint32_t bh0, bh1, bl0, bl1;
            if constexpr (X2) { tf32split(g0, bh0, bl0); tf32split(g1, bh1, bl1); }
            else { bh0 = f2tf32(g0); bh1 = f2tf32(g1); }
            mma8(acc[0][nt], ah[0], bh0, bh1);
            mma8(acc[1][nt], ah[1], bh0, bh1);
            if constexpr (X2) {
                mma8(acc[0][nt], al[0], bh0, bh1);
                mma8(acc[1][nt], al[1], bh0, bh1);
                mma8(acc[0][nt], ah[0], bl0, bl1);
                mma8(acc[1][nt], ah[1], bl0, bl1);
            }
        }
    }
    #pragma unroll
    for (int mt = 0; mt < 2; mt++)
        #pragma unroll
        for (int nt = 0; nt < 8; nt++) {
            int r = wm * 32 + mt * 16 + grp;
            int c = wn * 64 + nt * 8 + tq * 2;
            fe(r, c, acc[mt][nt][0], acc[mt][nt][1]);
            fe(r + 8, c, acc[mt][nt][2], acc[mt][nt][3]);
        }
}

// bf16-fragment-packed M index for mma.m16n8k16: element pair (r, c|c+1) ->
// word [kt(8)][mtile(8)][lane(32)][q(4)], q = qhi*2 + qlo.
__device__ __forceinline__ int mh_index(int r, int c) {
    int kt = c >> 4, p = (c & 15) >> 1, qhi = p >> 2, tqw = p & 3;
    int mtile = r >> 4, qlo = (r & 15) >> 3, grp7 = r & 7;
    return ((kt * 8 + mtile) * 32 + grp7 * 4 + tqw) * 4 + qhi * 2 + qlo;
}

__global__ __launch_bounds__(256) void k_chain(
    const float* __restrict__ Wq, const float* __restrict__ bq,
    const float* __restrict__ Wk, const float* __restrict__ bk,
    const float* __restrict__ Wv, const float* __restrict__ bv,
    const float* __restrict__ Wo, const float* __restrict__ bo,
    const float* __restrict__ gamma) {
    extern __shared__ float sm[];
    float* sA = sm;                 // 128 x LDSM
    float* sB = sm + NCH * LDSM;    // 128 x LDSM
    __shared__ float s_s[NCH], s_qs[NCH], s_ks[NCH], s_av[NCH];
    __shared__ float s_bq[NCH], s_bk[NCH], s_bv[NCH];

    int b = blockIdx.x, t = threadIdx.x;
    int lane = t & 31, wid = t >> 5;
    int grp = lane >> 2, tq = lane & 3;
    int wm = wid & 3, wn = wid >> 2;

    if (t < NCH) {
        s_s[t] = g_s[b * NCH + t];
        s_bq[t] = bq[t]; s_bk[t] = bk[t]; s_bv[t] = bv[t];
    }
    __syncthreads();

    // qs = Wq s, ks = Wk s
    {
        int d = t & 127;
        const float* W = (t < NCH) ? Wq : Wk;
        float a = 0.f;
        #pragma unroll 8
        for (int c = 0; c < NCH; c++) a += __ldg(&W[d * NCH + c]) * s_s[c];
        if (t < NCH) s_qs[d] = a; else s_ks[d] = a;
    }

    // G -> sA
    for (int i = t; i < NCH * 32; i += 256) {
        int r = i >> 5, c = (i & 31) << 2;
        *(float4*)(sA + r * LDSM + c) =
            *(const float4*)(g_G + (size_t)b * NCH * NCH + r * NCH + c);
    }
    __syncthreads();

    // T1 = Wq * G -> sB   (tf32x2)
    chain_mm<true>(
        [&](int r, int k) { return __ldg(&Wq[r * NCH + k]); },
        [&](int n, int k) { return sA[k * LDSM + n]; },
        [&](int r, int c, float v0, float v1) {
            sB[r * LDSM + c] = v0; sB[r * LDSM + c + 1] = v1;
        }, wm, wn, grp, tq);
    __syncthreads();

    // E = T1 * Wk^T + rank-1 -> sA   (tf32x2)
    chain_mm<true>(
        [&](int r, int k) { return sB[r * LDSM + k]; },
        [&](int n, int k) { return __ldg(&Wk[n * NCH + k]); },
        [&](int r, int c, float v0, float v1) {
            sA[r * LDSM + c] = v0 + s_qs[r] * s_bk[c]
                             + s_bq[r] * (s_ks[c] + (float)NTOK * s_bk[c]);
            sA[r * LDSM + c + 1] = v1 + s_qs[r] * s_bk[c + 1]
                             + s_bq[r] * (s_ks[c + 1] + (float)NTOK * s_bk[c + 1]);
        }, wm, wn, grp, tq);
    __syncthreads();

    // softmax rows of sA
    for (int r = wid; r < NCH; r += 8) {
        float4 v = *(float4*)(sA + r * LDSM + lane * 4);
        float m = fmaxf(fmaxf(v.x, v.y), fmaxf(v.z, v.w));
        #pragma unroll
        for (int o = 16; o; o >>= 1) m = fmaxf(m, __shfl_xor_sync(0xffffffffu, m, o));
        float e0 = __expf(v.x - m), e1 = __expf(v.y - m);
        float e2 = __expf(v.z - m), e3 = __expf(v.w - m);
        float s2 = e0 + e1 + e2 + e3;
        #pragma unroll
        for (int o = 16; o; o >>= 1) s2 += __shfl_xor_sync(0xffffffffu, s2, o);
        float inv = 1.f / s2;
        v.x = e0 * inv; v.y = e1 * inv; v.z = e2 * inv; v.w = e3 * inv;
        *(float4*)(sA + r * LDSM + lane * 4) = v;
    }
    __syncthreads();

    // av = A * bv
    if (t < NCH) {
        float a = 0.f;
        #pragma unroll 8
        for (int e = 0; e < NCH; e++) a += sA[t * LDSM + e] * s_bv[e];
        s_av[t] = a;
    }
    __syncthreads();

    // U = A * Wv -> sB  (tf32)
    chain_mm<false>(
        [&](int r, int k) { return sA[r * LDSM + k]; },
        [&](int n, int k) { return __ldg(&Wv[k * NCH + n]); },
        [&](int r, int c, float v0, float v1) {
            sB[r * LDSM + c] = v0; sB[r * LDSM + c + 1] = v1;
        }, wm, wn, grp, tq);
    __syncthreads();

    float gmv = __ldg(&gamma[0]);

    // M = gamma * Wo * U -> g_Mh (bf16x2, fragment-packed)
    chain_mm<false>(
        [&](int r, int k) { return __ldg(&Wo[r * NCH + k]); },
        [&](int n, int k) { return sB[k * LDSM + n]; },
        [&](int r, int c, float v0, float v1) {
            g_Mh[b * 8192 + mh_index(r, c)] = packbf16(gmv * v0, gmv * v1);
        }, wm, wn, grp, tq);

    // cvec = gamma * (Wo av + bo)
    if (t < NCH) {
        float a = 0.f;
        #pragma unroll 8
        for (int h = 0; h < NCH; h++) a += __ldg(&Wo[t * NCH + h]) * s_av[h];
        g_cvec[b * NCH + t] = gmv * (a + bo[t]);
    }
}

// ---------------------------------------------------------------------------
// Output: out = M * X + c 1^T + X
// 64-token tiles, 256 threads, 3 CTAs/SM. fp32 X quad-buffered via cp.async
// (residual stays exact), per-stage convert to token-major bf16 buffer,
// mma.m16n8k16 with pipelined bf16 A-frag LDG.128 from g_Mh.
// ---------------------------------------------------------------------------
__global__ __launch_bounds__(256, 3) void k_out(const float* __restrict__ x,
                                                float* __restrict__ out) {
    extern __shared__ float sx[];   // 4*32*XST fp32, then 64*BST2 b32 words
    uint32_t* shB = (uint32_t*)(sx + 4 * 32 * XST);

    int b = blockIdx.y;
    int tok0 = blockIdx.x * TOKT;
    int t = threadIdx.x;
    int lane = t & 31, wid = t >> 5;
    int grp = lane >> 2, tq = lane & 3;
    int wm = wid & 3, wn = wid >> 2;   // wn in {0,1}: 32-token half

    const float* xb = x + (size_t)b * NCH * NTOK;
    const uint4* Mh4 = (const uint4*)g_Mh + (size_t)b * 2048;

    int lrow = t >> 3, loff = (t & 7) << 3;   // 32 rows x 64 floats per stage
    const float* gsrc = xb + (size_t)lrow * NTOK + tok0 + loff;
    #pragma unroll
    for (int s = 0; s < 4; s++) {
        uint32_t sd = (uint32_t)__cvta_generic_to_shared(sx + s * 32 * XST + lrow * XST + loff);
        const float* p = gsrc + (size_t)s * 32 * NTOK;
        cpa16(sd, p);
        cpa16(sd + 16, p + 4);
        asm volatile("cp.async.commit_group;");
    }

    // prefetch A-frags for global ktile 0 (overlaps the stage-0 cp.async wait)
    uint4 nav0 = __ldg(&Mh4[(0 * 8 + wm * 2 + 0) * 32 + lane]);
    uint4 nav1 = __ldg(&Mh4[(0 * 8 + wm * 2 + 1) * 32 + lane]);

    // conversion mapping: token cn, word base ckw (16 words = 32 k per stage)
    int cn = t & 63, ckw = (t >> 6) << 2;

    float acc[2][4][4];
    #pragma unroll
    for (int i = 0; i < 2; i++)
        #pragma unroll
        for (int j = 0; j < 4; j++)
            #pragma unroll
            for (int k = 0; k < 4; k++) acc[i][j][k] = 0.f;

    #pragma unroll
    for (int s = 0; s < 4; s++) {
        if (s == 0)      asm volatile("cp.async.wait_group 3;");
        else if (s == 1) asm volatile("cp.async.wait_group 2;");
        else if (s == 2) asm volatile("cp.async.wait_group 1;");
        else             asm volatile("cp.async.wait_group 0;");
        __syncthreads();   // stage s ready; prior mma done (bf16 buf reusable)
        const float* cur = sx + s * 32 * XST;

        // convert stage s -> token-major bf16 buffer
        {
            uint32_t w[4];
            #pragma unroll
            for (int j = 0; j < 4; j++)
                w[j] = packbf16(cur[(2 * (ckw + j)) * XST + cn],
                                cur[(2 * (ckw + j) + 1) * XST + cn]);
            *(uint4*)(shB + cn * BST2 + ckw) = make_uint4(w[0], w[1], w[2], w[3]);
        }
        __syncthreads();

        #pragma unroll
        for (int ktl = 0; ktl < 2; ktl++) {   // 2 ktiles of K=16 per stage
            int ktg = s * 2 + ktl;
            uint4 av0 = nav0, av1 = nav1;
            if (ktg < 7) {
                nav0 = __ldg(&Mh4[((ktg + 1) * 8 + wm * 2 + 0) * 32 + lane]);
                nav1 = __ldg(&Mh4[((ktg + 1) * 8 + wm * 2 + 1) * 32 + lane]);
            }
            uint32_t a0[4] = {av0.x, av0.y, av0.z, av0.w};
            uint32_t a1[4] = {av1.x, av1.y, av1.z, av1.w};
            #pragma unroll
            for (int nt = 0; nt < 4; nt++) {
                int n0 = wn * 32 + nt * 8;
                uint32_t b0 = shB[(n0 + grp) * BST2 + ktl * 8 + tq];
                uint32_t b1 = shB[(n0 + grp) * BST2 + ktl * 8 + tq + 4];
                mma16(acc[0][nt], a0, b0, b1);
                mma16(acc[1][nt], a1, b0, b1);
            }
        }
    }

    float* ob = out + (size_t)b * NCH * NTOK;
    #pragma unroll
    for (int mt = 0; mt < 2; mt++) {
        int r  = wm * 32 + mt * 16 + grp;
        int r1 = r + 8;
        float cv0 = g_cvec[b * NCH + r];
        float cv1 = g_cvec[b * NCH + r1];
        const float* res0 = sx + (r >> 5) * 32 * XST + (r & 31) * XST;
        const float* res1 = sx + (r1 >> 5) * 32 * XST + (r1 & 31) * XST;
        #pragma unroll
        for (int nt = 0; nt < 4; nt++) {
            int cl = wn * 32 + nt * 8 + tq * 2;
            int c = tok0 + cl;
            size_t i0 = (size_t)r * NTOK + c;
            size_t i1 = (size_t)r1 * NTOK + c;
            ob[i0]     = acc[mt][nt][0] + cv0 + res0[cl];
            ob[i0 + 1] = acc[mt][nt][1] + cv0 + res0[cl + 1];
            ob[i1]     = acc[mt][nt][2] + cv1 + res1[cl];
            ob[i1 + 1] = acc[mt][nt][3] + cv1 + res1[cl + 1];
        }
    }
}

extern "C" void kernel_launch(void* const* d_in, const int* in_sizes, int n_in,
                              void* d_out, int out_size) {
    const float* x  = (const float*)d_in[0];
    const float* Wq = (const float*)d_in[1];
    const float* bq = (const float*)d_in[2];
    const float* Wk = (const float*)d_in[3];
    const float* bk = (const float*)d_in[4];
    const float* Wv = (const float*)d_in[5];
    const float* bv = (const float*)d_in[6];
    const float* Wo = (const float*)d_in[7];
    const float* bo = (const float*)d_in[8];
    const float* gm = (const float*)d_in[9];
    float* out = (float*)d_out;

    const int gram_smem  = (2 * NCH * GSTR) * 4 + NCH * BSTR * 4;   // 69632+18432=88064
    const int chain_smem = 2 * NCH * LDSM * 4;                      // 135168
    const int out_smem   = (4 * 32 * XST) * 4 + 64 * BST2 * 4;      // 36864+5120=41984
    cudaFuncSetAttribute(k_gram,  cudaFuncAttributeMaxDynamicSharedMemorySize, gram_smem);
    cudaFuncSetAttribute(k_chain, cudaFuncAttributeMaxDynamicSharedMemorySize, chain_smem);
    cudaFuncSetAttribute(k_out,   cudaFuncAttributeMaxDynamicSharedMemorySize, out_smem);

    k_gram<<<dim3(NCHUNK, NBAT), 256, gram_smem>>>(x);
    k_gred<<<(NBAT * NCH * NCH) / 256, 256>>>();
    k_chain<<<NBAT, 256, chain_smem>>>(Wq, bq, Wk, bk, Wv, bv, Wo, bo, gm);
    k_out<<<dim3(NTOK / TOKT, NBAT), 256, out_smem>>>(x, out);
}

// round 16
// speedup vs baseline: 1.3034x; 1.0068x over previous
#include <cuda_runtime.h>
#include <cstdint>
#include <cstddef>

// Channel self-attention via Gram restructuring:
//   G_b = X X^T, s_b = X 1
//   E = Wq G Wk^T + (Wq s) bk^T + bq (Wk s)^T + N bq bk^T ; A = softmax(E)
//   M = gamma * Wo (A Wv) ; c = gamma * (Wo A bv + bo)
//   out = M X + c 1^T + X
//
// Big GEMMs: bf16 mma.m16n8k16, fragments loaded via ldmatrix.x4 (4 frags per
// instruction vs 4 scalar LDS each). X staged fp32 via cp.async (residual +
// row sums fp32-exact), converted per stage to compact bf16 smem. M packed
// bf16x2 fragment-order by k_chain. E-path keeps tf32x2 rna splits.

#define NTOK 36864
#define NCH 128
#define NBAT 8
#define NCHUNK 36
#define CHUNK 1024
#define GW 64     /* gram stage width (cols) */
#define GSTR 68   /* gram fp32 stage stride (floats) */
#define BSTR 36   /* gram bf16 buf stride (b32 words); row stride 144 B (16-aligned) */
#define LDSM 132
#define TOKT 64
#define XST 72    /* k_out fp32 stage stride (floats) */
#define BST2 20   /* k_out bf16 buf stride (b32 words); row stride 80 B (16-aligned) */

__device__ float g_Gpart[NCHUNK * NBAT * NCH * NCH];
__device__ float g_spart[NCHUNK * NBAT * NCH];
__device__ float g_G[NBAT * NCH * NCH];
__device__ float g_s[NBAT * NCH];
__device__ uint32_t g_Mh[NBAT * 8192];   // M as bf16x2, mma-fragment-packed
__device__ float g_cvec[NBAT * NCH];

__device__ __forceinline__ uint32_t f2tf32(float f) {
    uint32_t u;
    asm("cvt.rna.tf32.f32 %0, %1;" : "=r"(u) : "f"(f));
    return u;
}

__device__ __forceinline__ void tf32split(float f, uint32_t& hi, uint32_t& lo) {
    uint32_t h;
    asm("cvt.rna.tf32.f32 %0, %1;" : "=r"(h) : "f"(f));
    float fh = __uint_as_float(h);
    float r = f - fh;
    uint32_t l;
    asm("cvt.rna.tf32.f32 %0, %1;" : "=r"(l) : "f"(r));
    hi = h; lo = l;
}

__device__ __forceinline__ uint32_t packbf16(float lo, float hi) {
    uint32_t r;
    asm("cvt.rn.bf16x2.f32 %0, %1, %2;" : "=r"(r) : "f"(hi), "f"(lo));
    return r;
}

__device__ __forceinline__ void mma8(float* d, const uint32_t* a, uint32_t b0, uint32_t b1) {
    asm volatile(
        "mma.sync.aligned.m16n8k8.row.col.f32.tf32.tf32.f32 "
        "{%0,%1,%2,%3},{%4,%5,%6,%7},{%8,%9},{%0,%1,%2,%3};"
        : "+f"(d[0]), "+f"(d[1]), "+f"(d[2]), "+f"(d[3])
        : "r"(a[0]), "r"(a[1]), "r"(a[2]), "r"(a[3]), "r"(b0), "r"(b1));
}

__device__ __forceinline__ void mma16(float* d, const uint32_t* a, uint32_t b0, uint32_t b1) {
    asm volatile(
        "mma.sync.aligned.m16n8k16.row.col.f32.bf16.bf16.f32 "
        "{%0,%1,%2,%3},{%4,%5,%6,%7},{%8,%9},{%0,%1,%2,%3};"
        : "+f"(d[0]), "+f"(d[1]), "+f"(d[2]), "+f"(d[3])
        : "r"(a[0]), "r"(a[1]), "r"(a[2]), "r"(a[3]), "r"(b0), "r"(b1));
}

__device__ __forceinline__ void ldsm4(uint32_t& r0, uint32_t& r1, uint32_t& r2,
                                      uint32_t& r3, uint32_t addr) {
    asm volatile("ldmatrix.sync.aligned.m8n8.x4.shared.b16 {%0,%1,%2,%3}, [%4];"
                 : "=r"(r0), "=r"(r1), "=r"(r2), "=r"(r3) : "r"(addr));
}

__device__ __forceinline__ void cpa16(uint32_t dst, const void* src) {
    asm volatile("cp.async.cg.shared.global [%0],[%1],16;" :: "r"(dst), "l"(src));
}

__device__ __forceinline__ uint32_t smem_u32(const void* p) {
    uint32_t a;
    asm("{ .reg .u64 t; cvta.to.shared.u64 t, %1; cvt.u32.u64 %0, t; }" : "=r"(a) : "l"(p));
    return a;
}

// ---------------------------------------------------------------------------
// Gram: per (chunk, batch) block computes 128x128 partial X X^T over 1024 cols
// (16 stages of 64). fp32 cp.async staging (double-buffered), per-stage
// convert to bf16 buffer, mma.m16n8k16 with ldmatrix.x4 fragment loads.
// Deterministic. 2 CTAs/SM.
// ---------------------------------------------------------------------------
__global__ __launch_bounds__(256, 2) void k_gram(const float* __restrict__ x) {
    extern __shared__ float sb[];
    // [0, 2*128*GSTR) fp32 stages; then 128*BSTR b32 words bf16 buffer
    uint32_t* sh = (uint32_t*)(sb + 2 * NCH * GSTR);

    int b = blockIdx.y, ch = blockIdx.x;
    int t = threadIdx.x;
    int lrow = t >> 1, lcol = (t & 1) << 5;
    int lane = t & 31, wid = t >> 5;
    int grp = lane >> 2, tq = lane & 3;
    int wm = wid & 3, wn = wid >> 2;

    const float* gsrc = x + (size_t)b * NCH * NTOK + (size_t)lrow * NTOK
                          + (size_t)ch * CHUNK + lcol;
    uint32_t sd0 = (uint32_t)__cvta_generic_to_shared(sb + lrow * GSTR + lcol);
    uint32_t sd1 = (uint32_t)__cvta_generic_to_shared(sb + NCH * GSTR + lrow * GSTR + lcol);

    // ldmatrix lane addresses (constant across stages; kt adds 32 B)
    uint32_t shb = smem_u32(sh);
    uint32_t aad[2], bad[4];
    #pragma unroll
    for (int mt = 0; mt < 2; mt++)
        aad[mt] = shb + ((wm * 32 + mt * 16 + (lane & 15)) * BSTR
                         + ((lane >> 4) << 2)) * 4;
    #pragma unroll
    for (int p = 0; p < 4; p++)
        bad[p] = shb + ((wn * 64 + p * 16 + (lane & 7) + ((lane >> 4) << 3)) * BSTR
                        + (((lane >> 3) & 1) << 2)) * 4;

    float acc[2][8][4];
    #pragma unroll
    for (int i = 0; i < 2; i++)
        #pragma unroll
        for (int j = 0; j < 8; j++)
            #pragma unroll
            for (int k = 0; k < 4; k++) acc[i][j][k] = 0.f;
    float rsum = 0.f;

    #pragma unroll
    for (int j = 0; j < 8; j++) cpa16(sd0 + j * 16, gsrc + j * 4);
    asm volatile("cp.async.commit_group;");

    const int NST = CHUNK / GW;  // 16
    for (int s = 0; s < NST; s++) {
        if (s + 1 < NST) {
            uint32_t dd = ((s + 1) & 1) ? sd1 : sd0;
            const float* p = gsrc + (s + 1) * GW;
            #pragma unroll
            for (int j = 0; j < 8; j++) cpa16(dd + j * 16, p + j * 4);
            asm volatile("cp.async.commit_group;");
            asm volatile("cp.async.wait_group 1;");
        } else {
            asm volatile("cp.async.wait_group 0;");
        }
        __syncthreads();   // fp32 stage s ready; all warps done with prior mma
        const float* cur = sb + (s & 1) * NCH * GSTR;

        // convert stage s -> bf16 buffer (+ row-sum accumulation, fp32 exact)
        {
            const float4* rp4 = (const float4*)(cur + lrow * GSTR + lcol);
            uint32_t w[16];
            #pragma unroll
            for (int i = 0; i < 8; i++) {
                float4 v = rp4[i];
                rsum += v.x + v.y + v.z + v.w;
                w[2 * i]     = packbf16(v.x, v.y);
                w[2 * i + 1] = packbf16(v.z, v.w);
            }
            uint4* dst = (uint4*)(sh + lrow * BSTR + ((t & 1) << 4));
            #pragma unroll
            for (int j = 0; j < 4; j++)
                dst[j] = make_uint4(w[4 * j], w[4 * j + 1], w[4 * j + 2], w[4 * j + 3]);
        }
        __syncthreads();   // bf16 buffer ready

        #pragma unroll
        for (int kt = 0; kt < 4; kt++) {   // 4 ktiles of K=16
            uint32_t a[2][4];
            ldsm4(a[0][0], a[0][1], a[0][2], a[0][3], aad[0] + kt * 32);
            ldsm4(a[1][0], a[1][1], a[1][2], a[1][3], aad[1] + kt * 32);
            #pragma unroll
            for (int p = 0; p < 4; p++) {
                uint32_t q0, q1, q2, q3;
                ldsm4(q0, q1, q2, q3, bad[p] + kt * 32);
                mma16(acc[0][2 * p],     a[0], q0, q1);
                mma16(acc[0][2 * p + 1], a[0], q2, q3);
                mma16(acc[1][2 * p],     a[1], q0, q1);
                mma16(acc[1][2 * p + 1], a[1], q2, q3);
            }
        }
        // next stage's top barrier fences bf16-buffer reuse
    }

    float* gp = g_Gpart + ((size_t)ch * NBAT + b) * NCH * NCH;
    #pragma unroll
    for (int mt = 0; mt < 2; mt++) {
        #pragma unroll
        for (int nt = 0; nt < 8; nt++) {
            int r = wm * 32 + mt * 16 + grp;
            int c = wn * 64 + nt * 8 + tq * 2;
            gp[r * NCH + c]           = acc[mt][nt][0];
            gp[r * NCH + c + 1]       = acc[mt][nt][1];
            gp[(r + 8) * NCH + c]     = acc[mt][nt][2];
            gp[(r + 8) * NCH + c + 1] = acc[mt][nt][3];
        }
    }
    rsum += __shfl_xor_sync(0xffffffffu, rsum, 1);
    if ((t & 1) == 0) g_spart[(ch * NBAT + b) * NCH + lrow] = rsum;
}

__global__ void k_gred() {
    int j = blockIdx.x * 256 + threadIdx.x;
    float a = 0.f;
    #pragma unroll
    for (int ch = 0; ch < NCHUNK; ch++) a += g_Gpart[(size_t)ch * (NBAT * NCH * NCH) + j];
    g_G[j] = a;
    if (j < NBAT * NCH) {
        float t2 = 0.f;
        #pragma unroll
        for (int ch = 0; ch < NCHUNK; ch++) t2 += g_spart[ch * (NBAT * NCH) + j];
        g_s[j] = t2;
    }
}

// ---------------------------------------------------------------------------
// Fused small chain: one block per batch, all 128x128 matmuls via MMA in smem.
// ---------------------------------------------------------------------------
template<bool X2, class FA, class FB, class FE>
__device__ __forceinline__ void chain_mm(FA fa, FB fb, FE fe,
                                         int wm, int wn, int grp, int tq) {
    float acc[2][8][4];
    #pragma unroll
    for (int i = 0; i < 2; i++)
        #pragma unroll
        for (int j = 0; j < 8; j++)
            #pragma unroll
            for (int k = 0; k < 4; k++) acc[i][j][k] = 0.f;

    for (int kk = 0; kk < NCH; kk += 8) {
        uint32_t ah[2][4], al[2][4];
        #pragma unroll
        for (int mt = 0; mt < 2; mt++) {
            int r0 = wm * 32 + mt * 16;
            #pragma unroll
            for (int q = 0; q < 4; q++) {
                int rr = r0 + grp + ((q & 1) ? 8 : 0);
                int kc = kk + tq + ((q >> 1) ? 4 : 0);
                float f = fa(rr, kc);
                if constexpr (X2) tf32split(f, ah[mt][q], al[mt][q]);
                else ah[mt][q] = f2tf32(f);
            }
        }
        #pragma unroll
        for (int nt = 0; nt < 8; nt++) {
            int n = wn * 64 + nt * 8 + grp;
            float g0 = fb(n, kk + tq);
            float g1 = fb(n, kk + tq + 4);
            uint32_t bh0, bh1, bl0, bl1;
            if constexpr (X2) { tf32split(g0, bh0, bl0); tf32split(g1, bh1, bl1); }
            else { bh0 = f2tf32(g0); bh1 = f2tf32(g1); }
            mma8(acc[0][nt], ah[0], bh0, bh1);
            mma8(acc[1][nt], ah[1], bh0, bh1);
            if constexpr (X2) {
                mma8(acc[0][nt], al[0], bh0, bh1);
                mma8(acc[1][nt], al[1], bh0, bh1);
                mma8(acc[0][nt], ah[0], bl0, bl1);
                mma8(acc[1][nt], ah[1], bl0, bl1);
            }
        }
    }
    #pragma unroll
    for (int mt = 0; mt < 2; mt++)
        #pragma unroll
        for (int nt = 0; nt < 8; nt++) {
            int r = wm * 32 + mt * 16 + grp;
            int c = wn * 64 + nt * 8 + tq * 2;
            fe(r, c, acc[mt][nt][0], acc[mt][nt][1]);
            fe(r + 8, c, acc[mt][nt][2], acc[mt][nt][3]);
        }
}

// bf16-fragment-packed M index for mma.m16n8k16
__device__ __forceinline__ int mh_index(int r, int c) {
    int kt = c >> 4, p = (c & 15) >> 1, qhi = p >> 2, tqw = p & 3;
    int mtile = r >> 4, qlo = (r & 15) >> 3, grp7 = r & 7;
    return ((kt * 8 + mtile) * 32 + grp7 * 4 + tqw) * 4 + qhi * 2 + qlo;
}

__global__ __launch_bounds__(256) void k_chain(
    const float* __restrict__ Wq, const float* __restrict__ bq,
    const float* __restrict__ Wk, const float* __restrict__ bk,
    const float* __restrict__ Wv, const float* __restrict__ bv,
    const float* __restrict__ Wo, const float* __restrict__ bo,
    const float* __restrict__ gamma) {
    extern __shared__ float sm[];
    float* sA = sm;
    float* sB = sm + NCH * LDSM;
    __shared__ float s_s[NCH], s_qs[NCH], s_ks[NCH], s_av[NCH];
    __shared__ float s_bq[NCH], s_bk[NCH], s_bv[NCH];

    int b = blockIdx.x, t = threadIdx.x;
    int lane = t & 31, wid = t >> 5;
    int grp = lane >> 2, tq = lane & 3;
    int wm = wid & 3, wn = wid >> 2;

    if (t < NCH) {
        s_s[t] = g_s[b * NCH + t];
        s_bq[t] = bq[t]; s_bk[t] = bk[t]; s_bv[t] = bv[t];
    }
    __syncthreads();

    {
        int d = t & 127;
        const float* W = (t < NCH) ? Wq : Wk;
        float a = 0.f;
        #pragma unroll 8
        for (int c = 0; c < NCH; c++) a += __ldg(&W[d * NCH + c]) * s_s[c];
        if (t < NCH) s_qs[d] = a; else s_ks[d] = a;
    }

    for (int i = t; i < NCH * 32; i += 256) {
        int r = i >> 5, c = (i & 31) << 2;
        *(float4*)(sA + r * LDSM + c) =
            *(const float4*)(g_G + (size_t)b * NCH * NCH + r * NCH + c);
    }
    __syncthreads();

    chain_mm<true>(
        [&](int r, int k) { return __ldg(&Wq[r * NCH + k]); },
        [&](int n, int k) { return sA[k * LDSM + n]; },
        [&](int r, int c, float v0, float v1) {
            sB[r * LDSM + c] = v0; sB[r * LDSM + c + 1] = v1;
        }, wm, wn, grp, tq);
    __syncthreads();

    chain_mm<true>(
        [&](int r, int k) { return sB[r * LDSM + k]; },
        [&](int n, int k) { return __ldg(&Wk[n * NCH + k]); },
        [&](int r, int c, float v0, float v1) {
            sA[r * LDSM + c] = v0 + s_qs[r] * s_bk[c]
                             + s_bq[r] * (s_ks[c] + (float)NTOK * s_bk[c]);
            sA[r * LDSM + c + 1] = v1 + s_qs[r] * s_bk[c + 1]
                             + s_bq[r] * (s_ks[c + 1] + (float)NTOK * s_bk[c + 1]);
        }, wm, wn, grp, tq);
    __syncthreads();

    for (int r = wid; r < NCH; r += 8) {
        float4 v = *(float4*)(sA + r * LDSM + lane * 4);
        float m = fmaxf(fmaxf(v.x, v.y), fmaxf(v.z, v.w));
        #pragma unroll
        for (int o = 16; o; o >>= 1) m = fmaxf(m, __shfl_xor_sync(0xffffffffu, m, o));
        float e0 = __expf(v.x - m), e1 = __expf(v.y - m);
        float e2 = __expf(v.z - m), e3 = __expf(v.w - m);
        float s2 = e0 + e1 + e2 + e3;
        #pragma unroll
        for (int o = 16; o; o >>= 1) s2 += __shfl_xor_sync(0xffffffffu, s2, o);
        float inv = 1.f / s2;
        v.x = e0 * inv; v.y = e1 * inv; v.z = e2 * inv; v.w = e3 * inv;
        *(float4*)(sA + r * LDSM + lane * 4) = v;
    }
    __syncthreads();

    if (t < NCH) {
        float a = 0.f;
        #pragma unroll 8
        for (int e = 0; e < NCH; e++) a += sA[t * LDSM + e] * s_bv[e];
        s_av[t] = a;
    }
    __syncthreads();

    chain_mm<false>(
        [&](int r, int k) { return sA[r * LDSM + k]; },
        [&](int n, int k) { return __ldg(&Wv[k * NCH + n]); },
        [&](int r, int c, float v0, float v1) {
            sB[r * LDSM + c] = v0; sB[r * LDSM + c + 1] = v1;
        }, wm, wn, grp, tq);
    __syncthreads();

    float gmv = __ldg(&gamma[0]);

    chain_mm<false>(
        [&](int r, int k) { return __ldg(&Wo[r * NCH + k]); },
        [&](int n, int k) { return sB[k * LDSM + n]; },
        [&](int r, int c, float v0, float v1) {
            g_Mh[b * 8192 + mh_index(r, c)] = packbf16(gmv * v0, gmv * v1);
        }, wm, wn, grp, tq);

    if (t < NCH) {
        float a = 0.f;
        #pragma unroll 8
        for (int h = 0; h < NCH; h++) a += __ldg(&Wo[t * NCH + h]) * s_av[h];
        g_cvec[b * NCH + t] = gmv * (a + bo[t]);
    }
}

// ---------------------------------------------------------------------------
// Output: out = M * X + c 1^T + X
// 64-token tiles, 256 threads, 3 CTAs/SM. fp32 X quad-buffered via cp.async,
// per-stage convert to token-major bf16 buffer, mma.m16n8k16 with pipelined
// bf16 A-frag LDG.128 from g_Mh and ldmatrix.x4 B-frag loads.
// ---------------------------------------------------------------------------
__global__ __launch_bounds__(256, 3) void k_out(const float* __restrict__ x,
                                                float* __restrict__ out) {
    extern __shared__ float sx[];   // 4*32*XST fp32, then 64*BST2 b32 words
    uint32_t* shB = (uint32_t*)(sx + 4 * 32 * XST);

    int b = blockIdx.y;
    int tok0 = blockIdx.x * TOKT;
    int t = threadIdx.x;
    int lane = t & 31, wid = t >> 5;
    int grp = lane >> 2, tq = lane & 3;
    int wm = wid & 3, wn = wid >> 2;

    const float* xb = x + (size_t)b * NCH * NTOK;
    const uint4* Mh4 = (const uint4*)g_Mh + (size_t)b * 2048;

    int lrow = t >> 3, loff = (t & 7) << 3;
    const float* gsrc = xb + (size_t)lrow * NTOK + tok0 + loff;
    #pragma unroll
    for (int s = 0; s < 4; s++) {
        uint32_t sd = (uint32_t)__cvta_generic_to_shared(sx + s * 32 * XST + lrow * XST + loff);
        const float* p = gsrc + (size_t)s * 32 * NTOK;
        cpa16(sd, p);
        cpa16(sd + 16, p + 4);
        asm volatile("cp.async.commit_group;");
    }

    uint4 nav0 = __ldg(&Mh4[(0 * 8 + wm * 2 + 0) * 32 + lane]);
    uint4 nav1 = __ldg(&Mh4[(0 * 8 + wm * 2 + 1) * 32 + lane]);

    int cn = t & 63, ckw = (t >> 6) << 2;

    // ldmatrix B lane addresses (constant; ktl adds 32 B)
    uint32_t shb2 = smem_u32(shB);
    uint32_t bad[2];
    #pragma unroll
    for (int p = 0; p < 2; p++)
        bad[p] = shb2 + ((wn * 32 + p * 16 + (lane & 7) + ((lane >> 4) << 3)) * BST2
                         + (((lane >> 3) & 1) << 2)) * 4;

    float acc[2][4][4];
    #pragma unroll
    for (int i = 0; i < 2; i++)
        #pragma unroll
        for (int j = 0; j < 4; j++)
            #pragma unroll
            for (int k = 0; k < 4; k++) acc[i][j][k] = 0.f;

    #pragma unroll
    for (int s = 0; s < 4; s++) {
        if (s == 0)      asm volatile("cp.async.wait_group 3;");
        else if (s == 1) asm volatile("cp.async.wait_group 2;");
        else if (s == 2) asm volatile("cp.async.wait_group 1;");
        else             asm volatile("cp.async.wait_group 0;");
        __syncthreads();
        const float* cur = sx + s * 32 * XST;

        {
            uint32_t w[4];
            #pragma unroll
            for (int j = 0; j < 4; j++)
                w[j] = packbf16(cur[(2 * (ckw + j)) * XST + cn],
                                cur[(2 * (ckw + j) + 1) * XST + cn]);
            *(uint4*)(shB + cn * BST2 + ckw) = make_uint4(w[0], w[1], w[2], w[3]);
        }
        __syncthreads();

        #pragma unroll
        for (int ktl = 0; ktl < 2; ktl++) {
            int ktg = s * 2 + ktl;
            uint4 av0 = nav0, av1 = nav1;
            if (ktg < 7) {
                nav0 = __ldg(&Mh4[((ktg + 1) * 8 + wm * 2 + 0) * 32 + lane]);
                nav1 = __ldg(&Mh4[((ktg + 1) * 8 + wm * 2 + 1) * 32 + lane]);
            }
            uint32_t a0[4] = {av0.x, av0.y, av0.z, av0.w};
            uint32_t a1[4] = {av1.x, av1.y, av1.z, av1.w};
            #pragma unroll
            for (int p = 0; p < 2; p++) {
                uint32_t q0, q1, q2, q3;
                ldsm4(q0, q1, q2, q3, bad[p] + ktl * 32);
                mma16(acc[0][2 * p],     a0, q0, q1);
                mma16(acc[0][2 * p + 1], a0, q2, q3);
                mma16(acc[1][2 * p],     a1, q0, q1);
                mma16(acc[1][2 * p + 1], a1, q2, q3);
            }
        }
    }

    float* ob = out + (size_t)b * NCH * NTOK;
    #pragma unroll
    for (int mt = 0; mt < 2; mt++) {
        int r  = wm * 32 + mt * 16 + grp;
        int r1 = r + 8;
        float cv0 = g_cvec[b * NCH + r];
        float cv1 = g_cvec[b * NCH + r1];
        const float* res0 = sx + (r >> 5) * 32 * XST + (r & 31) * XST;
        const float* res1 = sx + (r1 >> 5) * 32 * XST + (r1 & 31) * XST;
        #pragma unroll
        for (int nt = 0; nt < 4; nt++) {
            int cl = wn * 32 + nt * 8 + tq * 2;
            int c = tok0 + cl;
            size_t i0 = (size_t)r * NTOK + c;
            size_t i1 = (size_t)r1 * NTOK + c;
            ob[i0]     = acc[mt][nt][0] + cv0 + res0[cl];
            ob[i0 + 1] = acc[mt][nt][1] + cv0 + res0[cl + 1];
            ob[i1]     = acc[mt][nt][2] + cv1 + res1[cl];
            ob[i1 + 1] = acc[mt][nt][3] + cv1 + res1[cl + 1];
        }
    }
}

extern "C" void kernel_launch(void* const* d_in, const int* in_sizes, int n_in,
                              void* d_out, int out_size) {
    const float* x  = (const float*)d_in[0];
    const float* Wq = (const float*)d_in[1];
    const float* bq = (const float*)d_in[2];
    const float* Wk = (const float*)d_in[3];
    const float* bk = (const float*)d_in[4];
    const float* Wv = (const float*)d_in[5];
    const float* bv = (const float*)d_in[6];
    const float* Wo = (const float*)d_in[7];
    const float* bo = (const float*)d_in[8];
    const float* gm = (const float*)d_in[9];
    float* out = (float*)d_out;

    const int gram_smem  = (2 * NCH * GSTR) * 4 + NCH * BSTR * 4;   // 88064
    const int chain_smem = 2 * NCH * LDSM * 4;                      // 135168
    const int out_smem   = (4 * 32 * XST) * 4 + 64 * BST2 * 4;      // 41984
    cudaFuncSetAttribute(k_gram,  cudaFuncAttributeMaxDynamicSharedMemorySize, gram_smem);
    cudaFuncSetAttribute(k_chain, cudaFuncAttributeMaxDynamicSharedMemorySize, chain_smem);
    cudaFuncSetAttribute(k_out,   cudaFuncAttributeMaxDynamicSharedMemorySize, out_smem);

    k_gram<<<dim3(NCHUNK, NBAT), 256, gram_smem>>>(x);
    k_gred<<<(NBAT * NCH * NCH) / 256, 256>>>();
    k_chain<<<NBAT, 256, chain_smem>>>(Wq, bq, Wk, bk, Wv, bv, Wo, bo, gm);
    k_out<<<dim3(NTOK / TOKT, NBAT), 256, out_smem>>>(x, out);
}

// round 17
// speedup vs baseline: 1.3064x; 1.0023x over previous
#include <cuda_runtime.h>
#include <cstdint>
#include <cstddef>

// Channel self-attention via Gram restructuring:
//   G_b = X X^T, s_b = X 1
//   E = Wq G Wk^T + (Wq s) bk^T + bq (Wk s)^T + N bq bk^T ; A = softmax(E)
//   M = gamma * Wo (A Wv) ; c = gamma * (Wo A bv + bo)
//   out = M X + c 1^T + X
//
// bf16 mma.m16n8k16 with ldmatrix.x4. Software-pipelined: each barrier
// interval converts stage s+1 (fp32->bf16) while mma-ing stage s — the two
// streams interleave, one barrier per stage. E-path keeps tf32x2 rna splits.

#define NTOK 36864
#define NCH 128
#define NBAT 8
#define NCHUNK 36
#define CHUNK 1024
#define GW 64     /* gram stage width (cols) */
#define GSTR 68   /* gram fp32 stage stride (floats) */
#define BSTR 36   /* gram bf16 buf stride (b32 words) */
#define HBW (NCH * BSTR)          /* words per gram bf16 buffer */
#define LDSM 132
#define TOKT 64
#define XST 72    /* k_out fp32 stage stride (floats) */
#define BST2 20   /* k_out bf16 buf stride (b32 words) */
#define HBW2 (64 * BST2)          /* words per k_out bf16 buffer */

__device__ float g_Gpart[NCHUNK * NBAT * NCH * NCH];
__device__ float g_spart[NCHUNK * NBAT * NCH];
__device__ float g_G[NBAT * NCH * NCH];
__device__ float g_s[NBAT * NCH];
__device__ uint32_t g_Mh[NBAT * 8192];   // M as bf16x2, mma-fragment-packed
__device__ float g_cvec[NBAT * NCH];

__device__ __forceinline__ uint32_t f2tf32(float f) {
    uint32_t u;
    asm("cvt.rna.tf32.f32 %0, %1;" : "=r"(u) : "f"(f));
    return u;
}

__device__ __forceinline__ void tf32split(float f, uint32_t& hi, uint32_t& lo) {
    uint32_t h;
    asm("cvt.rna.tf32.f32 %0, %1;" : "=r"(h) : "f"(f));
    float fh = __uint_as_float(h);
    float r = f - fh;
    uint32_t l;
    asm("cvt.rna.tf32.f32 %0, %1;" : "=r"(l) : "f"(r));
    hi = h; lo = l;
}

__device__ __forceinline__ uint32_t packbf16(float lo, float hi) {
    uint32_t r;
    asm("cvt.rn.bf16x2.f32 %0, %1, %2;" : "=r"(r) : "f"(hi), "f"(lo));
    return r;
}

__device__ __forceinline__ void mma8(float* d, const uint32_t* a, uint32_t b0, uint32_t b1) {
    asm volatile(
        "mma.sync.aligned.m16n8k8.row.col.f32.tf32.tf32.f32 "
        "{%0,%1,%2,%3},{%4,%5,%6,%7},{%8,%9},{%0,%1,%2,%3};"
        : "+f"(d[0]), "+f"(d[1]), "+f"(d[2]), "+f"(d[3])
        : "r"(a[0]), "r"(a[1]), "r"(a[2]), "r"(a[3]), "r"(b0), "r"(b1));
}

__device__ __forceinline__ void mma16(float* d, const uint32_t* a, uint32_t b0, uint32_t b1) {
    asm volatile(
        "mma.sync.aligned.m16n8k16.row.col.f32.bf16.bf16.f32 "
        "{%0,%1,%2,%3},{%4,%5,%6,%7},{%8,%9},{%0,%1,%2,%3};"
        : "+f"(d[0]), "+f"(d[1]), "+f"(d[2]), "+f"(d[3])
        : "r"(a[0]), "r"(a[1]), "r"(a[2]), "r"(a[3]), "r"(b0), "r"(b1));
}

__device__ __forceinline__ void ldsm4(uint32_t& r0, uint32_t& r1, uint32_t& r2,
                                      uint32_t& r3, uint32_t addr) {
    asm volatile("ldmatrix.sync.aligned.m8n8.x4.shared.b16 {%0,%1,%2,%3}, [%4];"
                 : "=r"(r0), "=r"(r1), "=r"(r2), "=r"(r3) : "r"(addr));
}

__device__ __forceinline__ void cpa16(uint32_t dst, const void* src) {
    asm volatile("cp.async.cg.shared.global [%0],[%1],16;" :: "r"(dst), "l"(src));
}

__device__ __forceinline__ uint32_t smem_u32(const void* p) {
    uint32_t a;
    asm("{ .reg .u64 t; cvta.to.shared.u64 t, %1; cvt.u32.u64 %0, t; }" : "=r"(a) : "l"(p));
    return a;
}

// ---------------------------------------------------------------------------
// Gram: per (chunk, batch) block computes 128x128 partial X X^T over 1024 cols
// (16 stages of 64). Pipelined: barrier -> issue cp.async s+2 -> wait s+1 ->
// convert s+1 (own-region reads) -> mma s. One barrier per stage. 2 CTAs/SM.
// ---------------------------------------------------------------------------
__global__ __launch_bounds__(256, 2) void k_gram(const float* __restrict__ x) {
    extern __shared__ float sb[];
    // [0, 2*128*GSTR) fp32 stages; then 2 x HBW b32 words bf16 buffers
    uint32_t* sh = (uint32_t*)(sb + 2 * NCH * GSTR);

    int b = blockIdx.y, ch = blockIdx.x;
    int t = threadIdx.x;
    int lrow = t >> 1, lcol = (t & 1) << 5;
    int lane = t & 31, wid = t >> 5;
    int grp = lane >> 2, tq = lane & 3;
    int wm = wid & 3, wn = wid >> 2;

    const float* gsrc = x + (size_t)b * NCH * NTOK + (size_t)lrow * NTOK
                          + (size_t)ch * CHUNK + lcol;
    uint32_t fd[2];
    fd[0] = (uint32_t)__cvta_generic_to_shared(sb + lrow * GSTR + lcol);
    fd[1] = (uint32_t)__cvta_generic_to_shared(sb + NCH * GSTR + lrow * GSTR + lcol);

    // ldmatrix lane addresses (buffer 0; (s&1)*HBW*4 selects buffer, kt adds 32 B)
    uint32_t shb = smem_u32(sh);
    uint32_t aad[2], bad[4];
    #pragma unroll
    for (int mt = 0; mt < 2; mt++)
        aad[mt] = shb + ((wm * 32 + mt * 16 + (lane & 15)) * BSTR
                         + ((lane >> 4) << 2)) * 4;
    #pragma unroll
    for (int p = 0; p < 4; p++)
        bad[p] = shb + ((wn * 64 + p * 16 + (lane & 7) + ((lane >> 4) << 3)) * BSTR
                        + (((lane >> 3) & 1) << 2)) * 4;

    float acc[2][8][4];
    #pragma unroll
    for (int i = 0; i < 2; i++)
        #pragma unroll
        for (int j = 0; j < 8; j++)
            #pragma unroll
            for (int k = 0; k < 4; k++) acc[i][j][k] = 0.f;
    float rsum = 0.f;

    // prologue: stages 0,1 in flight; convert stage 0
    #pragma unroll
    for (int j = 0; j < 8; j++) cpa16(fd[0] + j * 16, gsrc + j * 4);
    asm volatile("cp.async.commit_group;");
    #pragma unroll
    for (int j = 0; j < 8; j++) cpa16(fd[1] + j * 16, gsrc + GW + j * 4);
    asm volatile("cp.async.commit_group;");
    asm volatile("cp.async.wait_group 1;");   // stage 0 (own region)
    {
        const float4* rp4 = (const float4*)(sb + lrow * GSTR + lcol);
        uint32_t w[16];
        #pragma unroll
        for (int i = 0; i < 8; i++) {
            float4 v = rp4[i];
            rsum += v.x + v.y + v.z + v.w;
            w[2 * i]     = packbf16(v.x, v.y);
            w[2 * i + 1] = packbf16(v.z, v.w);
        }
        uint4* dst = (uint4*)(sh + lrow * BSTR + ((t & 1) << 4));
        #pragma unroll
        for (int j = 0; j < 4; j++)
            dst[j] = make_uint4(w[4 * j], w[4 * j + 1], w[4 * j + 2], w[4 * j + 3]);
    }

    const int NST = CHUNK / GW;  // 16
    for (int s = 0; s < NST; s++) {
        __syncthreads();   // prior iter's convert visible; h/f buffers free

        if (s + 2 < NST) {   // stage s+2 -> f[s&1] (its stage-s data consumed)
            uint32_t dd = fd[s & 1];
            const float* p = gsrc + (s + 2) * GW;
            #pragma unroll
            for (int j = 0; j < 8; j++) cpa16(dd + j * 16, p + j * 4);
            asm volatile("cp.async.commit_group;");
            asm volatile("cp.async.wait_group 1;");   // stage s+1 landed
        } else if (s + 1 < NST) {
            asm volatile("cp.async.wait_group 0;");
        }

        // convert stage s+1 -> bf16 buf (s+1)&1  (reads own cp.async region)
        if (s + 1 < NST) {
            const float4* rp4 = (const float4*)(sb + ((s + 1) & 1) * NCH * GSTR
                                                + lrow * GSTR + lcol);
            uint32_t w[16];
            #pragma unroll
            for (int i = 0; i < 8; i++) {
                float4 v = rp4[i];
                rsum += v.x + v.y + v.z + v.w;
                w[2 * i]     = packbf16(v.x, v.y);
                w[2 * i + 1] = packbf16(v.z, v.w);
            }
            uint4* dst = (uint4*)(sh + ((s + 1) & 1) * HBW + lrow * BSTR + ((t & 1) << 4));
            #pragma unroll
            for (int j = 0; j < 4; j++)
                dst[j] = make_uint4(w[4 * j], w[4 * j + 1], w[4 * j + 2], w[4 * j + 3]);
        }

        // mma stage s from bf16 buf s&1 (written before this iter's barrier)
        uint32_t boff = (uint32_t)(s & 1) * (HBW * 4);
        #pragma unroll
        for (int kt = 0; kt < 4; kt++) {
            uint32_t a[2][4];
            ldsm4(a[0][0], a[0][1], a[0][2], a[0][3], aad[0] + boff + kt * 32);
            ldsm4(a[1][0], a[1][1], a[1][2], a[1][3], aad[1] + boff + kt * 32);
            #pragma unroll
            for (int p = 0; p < 4; p++) {
                uint32_t q0, q1, q2, q3;
                ldsm4(q0, q1, q2, q3, bad[p] + boff + kt * 32);
                mma16(acc[0][2 * p],     a[0], q0, q1);
                mma16(acc[0][2 * p + 1], a[0], q2, q3);
                mma16(acc[1][2 * p],     a[1], q0, q1);
                mma16(acc[1][2 * p + 1], a[1], q2, q3);
            }
        }
    }

    float* gp = g_Gpart + ((size_t)ch * NBAT + b) * NCH * NCH;
    #pragma unroll
    for (int mt = 0; mt < 2; mt++) {
        #pragma unroll
        for (int nt = 0; nt < 8; nt++) {
            int r = wm * 32 + mt * 16 + grp;
            int c = wn * 64 + nt * 8 + tq * 2;
            gp[r * NCH + c]           = acc[mt][nt][0];
            gp[r * NCH + c + 1]       = acc[mt][nt][1];
            gp[(r + 8) * NCH + c]     = acc[mt][nt][2];
            gp[(r + 8) * NCH + c + 1] = acc[mt][nt][3];
        }
    }
    rsum += __shfl_xor_sync(0xffffffffu, rsum, 1);
    if ((t & 1) == 0) g_spart[(ch * NBAT + b) * NCH + lrow] = rsum;
}

__global__ void k_gred() {
    int j = blockIdx.x * 256 + threadIdx.x;
    float a = 0.f;
    #pragma unroll
    for (int ch = 0; ch < NCHUNK; ch++) a += g_Gpart[(size_t)ch * (NBAT * NCH * NCH) + j];
    g_G[j] = a;
    if (j < NBAT * NCH) {
        float t2 = 0.f;
        #pragma unroll
        for (int ch = 0; ch < NCHUNK; ch++) t2 += g_spart[ch * (NBAT * NCH) + j];
        g_s[j] = t2;
    }
}

// ---------------------------------------------------------------------------
// Fused small chain: one block per batch, all 128x128 matmuls via MMA in smem.
// ---------------------------------------------------------------------------
template<bool X2, class FA, class FB, class FE>
__device__ __forceinline__ void chain_mm(FA fa, FB fb, FE fe,
                                         int wm, int wn, int grp, int tq) {
    float acc[2][8][4];
    #pragma unroll
    for (int i = 0; i < 2; i++)
        #pragma unroll
        for (int j = 0; j < 8; j++)
            #pragma unroll
            for (int k = 0; k < 4; k++) acc[i][j][k] = 0.f;

    for (int kk = 0; kk < NCH; kk += 8) {
        uint32_t ah[2][4], al[2][4];
        #pragma unroll
        for (int mt = 0; mt < 2; mt++) {
            int r0 = wm * 32 + mt * 16;
            #pragma unroll
            for (int q = 0; q < 4; q++) {
                int rr = r0 + grp + ((q & 1) ? 8 : 0);
                int kc = kk + tq + ((q >> 1) ? 4 : 0);
                float f = fa(rr, kc);
                if constexpr (X2) tf32split(f, ah[mt][q], al[mt][q]);
                else ah[mt][q] = f2tf32(f);
            }
        }
        #pragma unroll
        for (int nt = 0; nt < 8; nt++) {
            int n = wn * 64 + nt * 8 + grp;
            float g0 = fb(n, kk + tq);
            float g1 = fb(n, kk + tq + 4);
            uint32_t bh0, bh1, bl0, bl1;
            if constexpr (X2) { tf32split(g0, bh0, bl0); tf32split(g1, bh1, bl1); }
            else { bh0 = f2tf32(g0); bh1 = f2tf32(g1); }
            mma8(acc[0][nt], ah[0], bh0, bh1);
            mma8(acc[1][nt], ah[1], bh0, bh1);
            if constexpr (X2) {
                mma8(acc[0][nt], al[0], bh0, bh1);
                mma8(acc[1][nt], al[1], bh0, bh1);
                mma8(acc[0][nt], ah[0], bl0, bl1);
                mma8(acc[1][nt], ah[1], bl0, bl1);
            }
        }
    }
    #pragma unroll
    for (int mt = 0; mt < 2; mt++)
        #pragma unroll
        for (int nt = 0; nt < 8; nt++) {
            int r = wm * 32 + mt * 16 + grp;
            int c = wn * 64 + nt * 8 + tq * 2;
            fe(r, c, acc[mt][nt][0], acc[mt][nt][1]);
            fe(r + 8, c, acc[mt][nt][2], acc[mt][nt][3]);
        }
}

// bf16-fragment-packed M index for mma.m16n8k16
__device__ __forceinline__ int mh_index(int r, int c) {
    int kt = c >> 4, p = (c & 15) >> 1, qhi = p >> 2, tqw = p & 3;
    int mtile = r >> 4, qlo = (r & 15) >> 3, grp7 = r & 7;
    return ((kt * 8 + mtile) * 32 + grp7 * 4 + tqw) * 4 + qhi * 2 + qlo;
}

__global__ __launch_bounds__(256) void k_chain(
    const float* __restrict__ Wq, const float* __restrict__ bq,
    const float* __restrict__ Wk, const float* __restrict__ bk,
    const float* __restrict__ Wv, const float* __restrict__ bv,
    const float* __restrict__ Wo, const float* __restrict__ bo,
    const float* __restrict__ gamma) {
    extern __shared__ float sm[];
    float* sA = sm;
    float* sB = sm + NCH * LDSM;
    __shared__ float s_s[NCH], s_qs[NCH], s_ks[NCH], s_av[NCH];
    __shared__ float s_bq[NCH], s_bk[NCH], s_bv[NCH];

    int b = blockIdx.x, t = threadIdx.x;
    int lane = t & 31, wid = t >> 5;
    int grp = lane >> 2, tq = lane & 3;
    int wm = wid & 3, wn = wid >> 2;

    if (t < NCH) {
        s_s[t] = g_s[b * NCH + t];
        s_bq[t] = bq[t]; s_bk[t] = bk[t]; s_bv[t] = bv[t];
    }
    __syncthreads();

    {
        int d = t & 127;
        const float* W = (t < NCH) ? Wq : Wk;
        float a = 0.f;
        #pragma unroll 8
        for (int c = 0; c < NCH; c++) a += __ldg(&W[d * NCH + c]) * s_s[c];
        if (t < NCH) s_qs[d] = a; else s_ks[d] = a;
    }

    for (int i = t; i < NCH * 32; i += 256) {
        int r = i >> 5, c = (i & 31) << 2;
        *(float4*)(sA + r * LDSM + c) =
            *(const float4*)(g_G + (size_t)b * NCH * NCH + r * NCH + c);
    }
    __syncthreads();

    chain_mm<true>(
        [&](int r, int k) { return __ldg(&Wq[r * NCH + k]); },
        [&](int n, int k) { return sA[k * LDSM + n]; },
        [&](int r, int c, float v0, float v1) {
            sB[r * LDSM + c] = v0; sB[r * LDSM + c + 1] = v1;
        }, wm, wn, grp, tq);
    __syncthreads();

    chain_mm<true>(
        [&](int r, int k) { return sB[r * LDSM + k]; },
        [&](int n, int k) { return __ldg(&Wk[n * NCH + k]); },
        [&](int r, int c, float v0, float v1) {
            sA[r * LDSM + c] = v0 + s_qs[r] * s_bk[c]
                             + s_bq[r] * (s_ks[c] + (float)NTOK * s_bk[c]);
            sA[r * LDSM + c + 1] = v1 + s_qs[r] * s_bk[c + 1]
                             + s_bq[r] * (s_ks[c + 1] + (float)NTOK * s_bk[c + 1]);
        }, wm, wn, grp, tq);
    __syncthreads();

    for (int r = wid; r < NCH; r += 8) {
        float4 v = *(float4*)(sA + r * LDSM + lane * 4);
        float m = fmaxf(fmaxf(v.x, v.y), fmaxf(v.z, v.w));
        #pragma unroll
        for (int o = 16; o; o >>= 1) m = fmaxf(m, __shfl_xor_sync(0xffffffffu, m, o));
        float e0 = __expf(v.x - m), e1 = __expf(v.y - m);
        float e2 = __expf(v.z - m), e3 = __expf(v.w - m);
        float s2 = e0 + e1 + e2 + e3;
        #pragma unroll
        for (int o = 16; o; o >>= 1) s2 += __shfl_xor_sync(0xffffffffu, s2, o);
        float inv = 1.f / s2;
        v.x = e0 * inv; v.y = e1 * inv; v.z = e2 * inv; v.w = e3 * inv;
        *(float4*)(sA + r * LDSM + lane * 4) = v;
    }
    __syncthreads();

    if (t < NCH) {
        float a = 0.f;
        #pragma unroll 8
        for (int e = 0; e < NCH; e++) a += sA[t * LDSM + e] * s_bv[e];
        s_av[t] = a;
    }
    __syncthreads();

    chain_mm<false>(
        [&](int r, int k) { return sA[r * LDSM + k]; },
        [&](int n, int k) { return __ldg(&Wv[k * NCH + n]); },
        [&](int r, int c, float v0, float v1) {
            sB[r * LDSM + c] = v0; sB[r * LDSM + c + 1] = v1;
        }, wm, wn, grp, tq);
    __syncthreads();

    float gmv = __ldg(&gamma[0]);

    chain_mm<false>(
        [&](int r, int k) { return __ldg(&Wo[r * NCH + k]); },
        [&](int n, int k) { return sB[k * LDSM + n]; },
        [&](int r, int c, float v0, float v1) {
            g_Mh[b * 8192 + mh_index(r, c)] = packbf16(gmv * v0, gmv * v1);
        }, wm, wn, grp, tq);

    if (t < NCH) {
        float a = 0.f;
        #pragma unroll 8
        for (int h = 0; h < NCH; h++) a += __ldg(&Wo[t * NCH + h]) * s_av[h];
        g_cvec[b * NCH + t] = gmv * (a + bo[t]);
    }
}

// ---------------------------------------------------------------------------
// Output: out = M * X + c 1^T + X
// 64-token tiles, 256 threads, 3 CTAs/SM. All 4 fp32 X stages resident
// (residual from smem); pipelined convert(s+1) + mma(s) in one barrier
// interval; double bf16 buffer; A-frags via pipelined LDG.128 from g_Mh,
// B-frags via ldmatrix.x4.
// ---------------------------------------------------------------------------
__global__ __launch_bounds__(256, 3) void k_out(const float* __restrict__ x,
                                                float* __restrict__ out) {
    extern __shared__ float sx[];   // 4*32*XST fp32, then 2*HBW2 b32 words
    uint32_t* shB = (uint32_t*)(sx + 4 * 32 * XST);

    int b = blockIdx.y;
    int tok0 = blockIdx.x * TOKT;
    int t = threadIdx.x;
    int lane = t & 31, wid = t >> 5;
    int grp = lane >> 2, tq = lane & 3;
    int wm = wid & 3, wn = wid >> 2;

    const float* xb = x + (size_t)b * NCH * NTOK;
    const uint4* Mh4 = (const uint4*)g_Mh + (size_t)b * 2048;

    int lrow = t >> 3, loff = (t & 7) << 3;
    const float* gsrc = xb + (size_t)lrow * NTOK + tok0 + loff;
    #pragma unroll
    for (int s = 0; s < 4; s++) {
        uint32_t sd = (uint32_t)__cvta_generic_to_shared(sx + s * 32 * XST + lrow * XST + loff);
        const float* p = gsrc + (size_t)s * 32 * NTOK;
        cpa16(sd, p);
        cpa16(sd + 16, p + 4);
        asm volatile("cp.async.commit_group;");
    }

    uint4 nav0 = __ldg(&Mh4[(0 * 8 + wm * 2 + 0) * 32 + lane]);
    uint4 nav1 = __ldg(&Mh4[(0 * 8 + wm * 2 + 1) * 32 + lane]);

    int cn = t & 63, ckw = (t >> 6) << 2;

    // ldmatrix B lane addresses (buffer 0; (s&1)*HBW2*4 selects buffer)
    uint32_t shb2 = smem_u32(shB);
    uint32_t bad[2];
    #pragma unroll
    for (int p = 0; p < 2; p++)
        bad[p] = shb2 + ((wn * 32 + p * 16 + (lane & 7) + ((lane >> 4) << 3)) * BST2
                         + (((lane >> 3) & 1) << 2)) * 4;

    float acc[2][4][4];
    #pragma unroll
    for (int i = 0; i < 2; i++)
        #pragma unroll
        for (int j = 0; j < 4; j++)
            #pragma unroll
            for (int k = 0; k < 4; k++) acc[i][j][k] = 0.f;

    // prologue: convert stage 0 -> bf16 buf 0
    asm volatile("cp.async.wait_group 3;");
    __syncthreads();
    {
        const float* cur = sx;
        uint32_t w[4];
        #pragma unroll
        for (int j = 0; j < 4; j++)
            w[j] = packbf16(cur[(2 * (ckw + j)) * XST + cn],
                            cur[(2 * (ckw + j) + 1) * XST + cn]);
        *(uint4*)(shB + cn * BST2 + ckw) = make_uint4(w[0], w[1], w[2], w[3]);
    }

    #pragma unroll
    for (int s = 0; s < 4; s++) {
        if (s == 0)      asm volatile("cp.async.wait_group 2;");
        else if (s == 1) asm volatile("cp.async.wait_group 1;");
        else if (s == 2) asm volatile("cp.async.wait_group 0;");
        __syncthreads();   // prior convert visible; bf16 buf (s+1)&1 free

        // convert stage s+1 -> bf16 buf (s+1)&1
        if (s + 1 < 4) {
            const float* cur = sx + (s + 1) * 32 * XST;
            uint32_t* dbuf = shB + ((s + 1) & 1) * HBW2;
            uint32_t w[4];
            #pragma unroll
            for (int j = 0; j < 4; j++)
                w[j] = packbf16(cur[(2 * (ckw + j)) * XST + cn],
                                cur[(2 * (ckw + j) + 1) * XST + cn]);
            *(uint4*)(dbuf + cn * BST2 + ckw) = make_uint4(w[0], w[1], w[2], w[3]);
        }

        // mma stage s from bf16 buf s&1
        uint32_t boff = (uint32_t)(s & 1) * (HBW2 * 4);
        #pragma unroll
        for (int ktl = 0; ktl < 2; ktl++) {
            int ktg = s * 2 + ktl;
            uint4 av0 = nav0, av1 = nav1;
            if (ktg < 7) {
                nav0 = __ldg(&Mh4[((ktg + 1) * 8 + wm * 2 + 0) * 32 + lane]);
                nav1 = __ldg(&Mh4[((ktg + 1) * 8 + wm * 2 + 1) * 32 + lane]);
            }
            uint32_t a0[4] = {av0.x, av0.y, av0.z, av0.w};
            uint32_t a1[4] = {av1.x, av1.y, av1.z, av1.w};
            #pragma unroll
            for (int p = 0; p < 2; p++) {
                uint32_t q0, q1, q2, q3;
                ldsm4(q0, q1, q2, q3, bad[p] + boff + ktl * 32);
                mma16(acc[0][2 * p],     a0, q0, q1);
                mma16(acc[0][2 * p + 1], a0, q2, q3);
                mma16(acc[1][2 * p],     a1, q0, q1);
                mma16(acc[1][2 * p + 1], a1, q2, q3);
            }
        }
    }

    float* ob = out + (size_t)b * NCH * NTOK;
    #pragma unroll
    for (int mt = 0; mt < 2; mt++) {
        int r  = wm * 32 + mt * 16 + grp;
        int r1 = r + 8;
        float cv0 = g_cvec[b * NCH + r];
        float cv1 = g_cvec[b * NCH + r1];
        const float* res0 = sx + (r >> 5) * 32 * XST + (r & 31) * XST;
        const float* res1 = sx + (r1 >> 5) * 32 * XST + (r1 & 31) * XST;
        #pragma unroll
        for (int nt = 0; nt < 4; nt++) {
            int cl = wn * 32 + nt * 8 + tq * 2;
            int c = tok0 + cl;
            size_t i0 = (size_t)r * NTOK + c;
            size_t i1 = (size_t)r1 * NTOK + c;
            ob[i0]     = acc[mt][nt][0] + cv0 + res0[cl];
            ob[i0 + 1] = acc[mt][nt][1] + cv0 + res0[cl + 1];
            ob[i1]     = acc[mt][nt][2] + cv1 + res1[cl];
            ob[i1 + 1] = acc[mt][nt][3] + cv1 + res1[cl + 1];
        }
    }
}

extern "C" void kernel_launch(void* const* d_in, const int* in_sizes, int n_in,
                              void* d_out, int out_size) {
    const float* x  = (const float*)d_in[0];
    const float* Wq = (const float*)d_in[1];
    const float* bq = (const float*)d_in[2];
    const float* Wk = (const float*)d_in[3];
    const float* bk = (const float*)d_in[4];
    const float* Wv = (const float*)d_in[5];
    const float* bv = (const float*)d_in[6];
    const float* Wo = (const float*)d_in[7];
    const float* bo = (const float*)d_in[8];
    const float* gm = (const float*)d_in[9];
    float* out = (float*)d_out;

    const int gram_smem  = (2 * NCH * GSTR) * 4 + 2 * HBW * 4;      // 69632+36864=106496
    const int chain_smem = 2 * NCH * LDSM * 4;                      // 135168
    const int out_smem   = (4 * 32 * XST) * 4 + 2 * HBW2 * 4;       // 36864+10240=47104
    cudaFuncSetAttribute(k_gram,  cudaFuncAttributeMaxDynamicSharedMemorySize, gram_smem);
    cudaFuncSetAttribute(k_chain, cudaFuncAttributeMaxDynamicSharedMemorySize, chain_smem);
    cudaFuncSetAttribute(k_out,   cudaFuncAttributeMaxDynamicSharedMemorySize, out_smem);

    k_gram<<<dim3(NCHUNK, NBAT), 256, gram_smem>>>(x);
    k_gred<<<(NBAT * NCH * NCH) / 256, 256>>>();
    k_chain<<<NBAT, 256, chain_smem>>>(Wq, bq, Wk, bk, Wv, bv, Wo, bo, gm);
    k_out<<<dim3(NTOK / TOKT, NBAT), 256, out_smem>>>(x, out);
}